// round 1
// baseline (speedup 1.0000x reference)
#include <cuda_runtime.h>
#include <math.h>
#include <stdint.h>

// ---------------- constants ----------------
#define D     512
#define NH    8
#define DK    64
#define BSZ   16
#define TTRG  64
#define TT    64
#define SSP   49
#define DFF   2048
#define NT    1024      /* B*Ttrg */
#define NV    50176     /* B*T*S  */
#define NBIG  65536     /* B*T*Ttrg */

// ---------------- scratch (device globals; allocation-free) ----------------
__device__ float g_big0[(size_t)NBIG * D];   // 128MB
__device__ float g_big1[(size_t)NBIG * D];
__device__ float g_big2[(size_t)NBIG * D];
__device__ float g_big3[(size_t)NBIG * D];
__device__ float g_ln [(size_t)NT * D];
__device__ float g_q  [(size_t)NT * D];
__device__ float g_o  [(size_t)NT * D];
__device__ float g_cur[(size_t)NT * D];
__device__ float g_ts [(size_t)NT * D];
__device__ float g_st [(size_t)NT * D];
__device__ float g_k  [(size_t)2048 * D];
__device__ float g_v  [(size_t)2048 * D];
__device__ float g_mid[(size_t)NT * DFF];

// ---------------- SGEMM: C[M,N] = A[M,K] @ W[K,N] + bias (+res) (+relu) ----
// M % BM == 0, N % BN == 0, K % BK == 0 guaranteed by caller.
// res (if non-null) is a [*,N] buffer indexed res_row = (row/resDiv)*64 + (row&63).
template<int BM,int BN,int BK,int TM,int TN>
__global__ void sgemm_kernel(int M, int N, int K,
                             const float* __restrict__ A,
                             const float* __restrict__ W,
                             const float* __restrict__ bias,
                             const float* res, int resDiv, int relu,
                             float* C)
{
    constexpr int THREADS = (BM/TM)*(BN/TN);
    __shared__ float As[BK][BM];
    __shared__ float Bs[BK][BN];
    const int tid = threadIdx.x;
    const int bm = blockIdx.y * BM;
    const int bn = blockIdx.x * BN;
    const int tc = tid % (BN/TN);
    const int tr = tid / (BN/TN);

    float acc[TM][TN];
    #pragma unroll
    for (int i=0;i<TM;i++)
        #pragma unroll
        for (int j=0;j<TN;j++) acc[i][j] = 0.f;

    constexpr int A_F4 = (BM*BK)/(4*THREADS);
    constexpr int B_F4 = (BK*BN)/(4*THREADS);

    for (int k0 = 0; k0 < K; k0 += BK) {
        #pragma unroll
        for (int t = 0; t < A_F4; t++) {
            int idx = tid + t*THREADS;
            int row = idx / (BK/4);
            int kq  = idx % (BK/4);
            float4 v = *(const float4*)(A + (size_t)(bm+row)*K + k0 + kq*4);
            As[kq*4+0][row] = v.x;
            As[kq*4+1][row] = v.y;
            As[kq*4+2][row] = v.z;
            As[kq*4+3][row] = v.w;
        }
        #pragma unroll
        for (int t = 0; t < B_F4; t++) {
            int idx = tid + t*THREADS;
            int kr = idx / (BN/4);
            int nq = idx % (BN/4);
            float4 v = *(const float4*)(W + (size_t)(k0+kr)*N + bn + nq*4);
            *(float4*)&Bs[kr][nq*4] = v;
        }
        __syncthreads();
        #pragma unroll
        for (int kk = 0; kk < BK; kk++) {
            float ra[TM], rb[TN];
            #pragma unroll
            for (int i=0;i<TM;i++) ra[i] = As[kk][tr*TM+i];
            #pragma unroll
            for (int j=0;j<TN;j++) rb[j] = Bs[kk][tc*TN+j];
            #pragma unroll
            for (int i=0;i<TM;i++)
                #pragma unroll
                for (int j=0;j<TN;j++) acc[i][j] += ra[i]*rb[j];
        }
        __syncthreads();
    }

    #pragma unroll
    for (int i=0;i<TM;i++) {
        int row = bm + tr*TM + i;
        const float* rrow = nullptr;
        if (res) {
            int rr = (row/resDiv)*64 + (row & 63);
            rrow = res + (size_t)rr*N;
        }
        #pragma unroll
        for (int j=0;j<TN;j++) {
            int col = bn + tc*TN + j;
            float v = acc[i][j] + bias[col];
            if (res)  v += rrow[col];
            if (relu) v = fmaxf(v, 0.f);
            C[(size_t)row*N + col] = v;
        }
    }
}

static void launch_gemm(const float* A, const float* W, const float* bias,
                        const float* res, int resDiv, int relu,
                        float* C, int M, int N, int K)
{
    if (M >= 8192 && (M % 128) == 0 && (N % 128) == 0) {
        dim3 grid(N/128, M/128);
        sgemm_kernel<128,128,16,8,8><<<grid,256>>>(M,N,K,A,W,bias,res,resDiv,relu,C);
    } else {
        dim3 grid(N/64, M/64);
        sgemm_kernel<64,64,16,4,4><<<grid,256>>>(M,N,K,A,W,bias,res,resDiv,relu,C);
    }
}

// ---------------- LayerNorm (row = 512 elems) --------------------------
__global__ void ln_kernel(const float* __restrict__ X,
                          const float* __restrict__ g,
                          const float* __restrict__ b,
                          float* __restrict__ Y)
{
    const int row = blockIdx.x;
    const int tid = threadIdx.x;
    const float* x = X + (size_t)row * D;
    float v0 = x[tid], v1 = x[tid+256];
    __shared__ float red[16];

    float s = v0 + v1;
    #pragma unroll
    for (int o=16;o>0;o>>=1) s += __shfl_xor_sync(0xffffffffu, s, o);
    if ((tid & 31) == 0) red[tid>>5] = s;
    __syncthreads();
    if (tid < 32) {
        float t = (tid < 8) ? red[tid] : 0.f;
        #pragma unroll
        for (int o=4;o>0;o>>=1) t += __shfl_xor_sync(0xffffffffu, t, o);
        if (tid == 0) red[8] = t;
    }
    __syncthreads();
    const float mean = red[8] * (1.f/512.f);
    const float d0 = v0 - mean, d1 = v1 - mean;
    s = d0*d0 + d1*d1;
    #pragma unroll
    for (int o=16;o>0;o>>=1) s += __shfl_xor_sync(0xffffffffu, s, o);
    if ((tid & 31) == 0) red[tid>>5] = s;
    __syncthreads();
    if (tid < 32) {
        float t = (tid < 8) ? red[tid] : 0.f;
        #pragma unroll
        for (int o=4;o>0;o>>=1) t += __shfl_xor_sync(0xffffffffu, t, o);
        if (tid == 0) red[9] = t;
    }
    __syncthreads();
    const float stdv = sqrtf(red[9] * (1.f/512.f));
    const float inv = 1.f / (stdv + 1e-6f);
    Y[(size_t)row*D + tid      ] = g[tid]     * d0 * inv + b[tid];
    Y[(size_t)row*D + tid + 256] = g[tid+256] * d1 * inv + b[tid+256];
}

// ---------------- generic strided attention ----------------------------
// grid = (nb, NH); block = 128 threads (4 warps).
// K/V row for (batch-unit i, key tk):  kBase(i) + tk*kStride,
//   kBase = (i/kDiv)*kOuter + (i%kDiv)
// Q row:  (i/qDiv)*Lq + tq ;  O row: i*Lq + tq.
// maskMode: 0 none; 1 row-mask mask[(i/maskDiv)*Lk + tk]; 2 full mask[(i*Lq+tq)*Lk+tk]
__global__ void attn_kernel(const float* __restrict__ Q,
                            const float* __restrict__ K,
                            const float* __restrict__ V,
                            float* __restrict__ O,
                            const int* __restrict__ mask,
                            int maskMode, int maskDiv,
                            int Lq, int Lk,
                            int qDiv, int kOuter, int kDiv, int kStride,
                            float scale)
{
    extern __shared__ float sm[];
    float* Ks = sm;                       // Lk*65
    float* Vs = Ks + Lk*65;               // Lk*65
    float* qs = Vs + Lk*65;               // 4*64
    float* ps = qs + 4*64;                // 4*Lk

    const int i = blockIdx.x;
    const int h = blockIdx.y;
    const int tid = threadIdx.x;
    const int lane = tid & 31;
    const int w = tid >> 5;

    const size_t kBase = (size_t)(i/kDiv)*kOuter + (size_t)(i%kDiv);

    for (int idx = tid; idx < Lk*64; idx += 128) {
        int tk = idx >> 6, d = idx & 63;
        size_t grow = (kBase + (size_t)tk*kStride)*D + h*DK + d;
        Ks[tk*65+d] = K[grow];
        Vs[tk*65+d] = V[grow];
    }
    __syncthreads();

    const int qb = (i/qDiv) * Lq;
    const int nj = (Lk + 31) >> 5;

    for (int tq = w; tq < Lq; tq += 4) {
        size_t qoff = (size_t)(qb + tq)*D + h*DK;
        qs[w*64 + lane]      = Q[qoff + lane];
        qs[w*64 + lane + 32] = Q[qoff + lane + 32];
        __syncwarp();

        float sc[4];
        #pragma unroll
        for (int j=0;j<4;j++) sc[j] = -INFINITY;

        for (int j=0;j<nj;j++) {
            int k = lane + (j<<5);
            if (k < Lk) {
                float dot = 0.f;
                const float* kr = Ks + k*65;
                const float* qq = qs + w*64;
                #pragma unroll
                for (int d=0; d<64; d++) dot += qq[d]*kr[d];
                dot *= scale;
                if (maskMode == 1) {
                    if (mask[(size_t)(i/maskDiv)*Lk + k] == 0) dot = -1e9f;
                } else if (maskMode == 2) {
                    if (mask[((size_t)i*Lq + tq)*Lk + k] == 0) dot = -1e9f;
                }
                sc[j] = dot;
            }
        }
        float mx = -INFINITY;
        for (int j=0;j<nj;j++) mx = fmaxf(mx, sc[j]);
        #pragma unroll
        for (int o=16;o>0;o>>=1) mx = fmaxf(mx, __shfl_xor_sync(0xffffffffu, mx, o));

        float e[4]; float sum = 0.f;
        for (int j=0;j<nj;j++) {
            e[j] = (sc[j] == -INFINITY) ? 0.f : __expf(sc[j] - mx);
            sum += e[j];
        }
        #pragma unroll
        for (int o=16;o>0;o>>=1) sum += __shfl_xor_sync(0xffffffffu, sum, o);
        const float inv = 1.f / sum;
        for (int j=0;j<nj;j++) {
            int k = lane + (j<<5);
            if (k < Lk) ps[w*Lk + k] = e[j] * inv;
        }
        __syncwarp();

        float o0 = 0.f, o1 = 0.f;
        for (int k=0;k<Lk;k++) {
            float p = ps[w*Lk + k];
            o0 += p * Vs[k*65 + lane];
            o1 += p * Vs[k*65 + lane + 32];
        }
        size_t orow = ((size_t)i*Lq + tq)*D + h*DK;
        O[orow + lane]      = o0;
        O[orow + lane + 32] = o1;
        __syncwarp();
    }
}

static void launch_attn(const float* Q, const float* K, const float* V, float* O,
                        const int* mask, int maskMode, int maskDiv,
                        int nb, int Lq, int Lk,
                        int qDiv, int kOuter, int kDiv, int kStride)
{
    dim3 grid(nb, NH);
    size_t smem = (size_t)(2*Lk*65 + 4*64 + 4*Lk) * sizeof(float);
    attn_kernel<<<grid, 128, smem>>>(Q, K, V, O, mask, maskMode, maskDiv,
                                     Lq, Lk, qDiv, kOuter, kDiv, kStride, 0.125f);
}

// ---------------- elementwise add ----------------
__global__ void add_kernel(const float* __restrict__ a, const float* __restrict__ b,
                           float* __restrict__ c, int n)
{
    int i = blockIdx.x*256 + threadIdx.x;
    if (i < n) c[i] = a[i] + b[i];
}

// ---------------- driver ----------------
extern "C" void kernel_launch(void* const* d_in, const int* in_sizes, int n_in,
                              void* d_out, int out_size)
{
    const float* x        = (const float*)d_in[0];
    const float* vft      = (const float*)d_in[1];
    const float* enc_his  = (const float*)d_in[2];
    const float* enc_cap  = (const float*)d_in[3];
    const float* enc_qry  = (const float*)d_in[4];
    const int*   trg_mask = (const int*)  d_in[5];
    const int*   his_mask = (const int*)  d_in[6];
    const int*   cap_mask = (const int*)  d_in[7];
    const int*   qry_mask = (const int*)  d_in[8];
    const int*   tmp_mask = (const int*)  d_in[9];
    const float* attn_w   = (const float*)d_in[10];
    const float* attn_b   = (const float*)d_in[11];
    const float* ff_w1    = (const float*)d_in[12];
    const float* ff_b1    = (const float*)d_in[13];
    const float* ff_w2    = (const float*)d_in[14];
    const float* ff_b2    = (const float*)d_in[15];
    const float* ln_g     = (const float*)d_in[16];
    const float* ln_b     = (const float*)d_in[17];
    float* outp = (float*)d_out;

    float *big0,*big1,*big2,*big3,*lnb,*qb,*ob,*cur,*ts,*st,*kb,*vb,*mid;
    cudaGetSymbolAddress((void**)&big0, g_big0);
    cudaGetSymbolAddress((void**)&big1, g_big1);
    cudaGetSymbolAddress((void**)&big2, g_big2);
    cudaGetSymbolAddress((void**)&big3, g_big3);
    cudaGetSymbolAddress((void**)&lnb,  g_ln);
    cudaGetSymbolAddress((void**)&qb,   g_q);
    cudaGetSymbolAddress((void**)&ob,   g_o);
    cudaGetSymbolAddress((void**)&cur,  g_cur);
    cudaGetSymbolAddress((void**)&ts,   g_ts);
    cudaGetSymbolAddress((void**)&st,   g_st);
    cudaGetSymbolAddress((void**)&kb,   g_k);
    cudaGetSymbolAddress((void**)&vb,   g_v);
    cudaGetSymbolAddress((void**)&mid,  g_mid);

    cudaFuncSetAttribute(attn_kernel, cudaFuncAttributeMaxDynamicSharedMemorySize, 73728);

    #define WATT(l,j) (attn_w + ((size_t)(l)*4+(j))*D*D)
    #define BATT(l,j) (attn_b + ((size_t)(l)*4+(j))*D)

    // ===== MHA0: self-attn, causal mask =====
    ln_kernel<<<NT,256>>>(x, ln_g + 0*D, ln_b + 0*D, lnb);
    launch_gemm(lnb, WATT(0,0), BATT(0,0), nullptr,1,0, qb, NT, D, D);
    launch_gemm(lnb, WATT(0,1), BATT(0,1), nullptr,1,0, kb, NT, D, D);
    launch_gemm(lnb, WATT(0,2), BATT(0,2), nullptr,1,0, vb, NT, D, D);
    launch_attn(qb, kb, vb, ob, trg_mask, 2, 1, BSZ, TTRG, TTRG, 1, TTRG, 1, 1);
    launch_gemm(ob, WATT(0,3), BATT(0,3), x, 64, 0, cur, NT, D, D);

    // ===== MHA1: cross-attn on encoded_his (Lk=128) =====
    ln_kernel<<<NT,256>>>(cur, ln_g + 1*D, ln_b + 1*D, lnb);
    launch_gemm(lnb,     WATT(1,0), BATT(1,0), nullptr,1,0, qb, NT,   D, D);
    launch_gemm(enc_his, WATT(1,1), BATT(1,1), nullptr,1,0, kb, 2048, D, D);
    launch_gemm(enc_his, WATT(1,2), BATT(1,2), nullptr,1,0, vb, 2048, D, D);
    launch_attn(qb, kb, vb, ob, his_mask, 1, 1, BSZ, TTRG, 128, 1, 128, 1, 1);
    launch_gemm(ob, WATT(1,3), BATT(1,3), cur, 64, 0, cur, NT, D, D);

    // ===== MHA2: cross-attn on encoded_cap (Lk=64) =====
    ln_kernel<<<NT,256>>>(cur, ln_g + 2*D, ln_b + 2*D, lnb);
    launch_gemm(lnb,     WATT(2,0), BATT(2,0), nullptr,1,0, qb, NT,   D, D);
    launch_gemm(enc_cap, WATT(2,1), BATT(2,1), nullptr,1,0, kb, 1024, D, D);
    launch_gemm(enc_cap, WATT(2,2), BATT(2,2), nullptr,1,0, vb, 1024, D, D);
    launch_attn(qb, kb, vb, ob, cap_mask, 1, 1, BSZ, TTRG, 64, 1, 64, 1, 1);
    launch_gemm(ob, WATT(2,3), BATT(2,3), cur, 64, 0, cur, NT, D, D);

    // ===== MHA3: cross-attn on encoded_query (Lk=32) -> mm (kept in cur) =====
    ln_kernel<<<NT,256>>>(cur, ln_g + 3*D, ln_b + 3*D, lnb);
    launch_gemm(lnb,     WATT(3,0), BATT(3,0), nullptr,1,0, qb, NT,  D, D);
    launch_gemm(enc_qry, WATT(3,1), BATT(3,1), nullptr,1,0, kb, 512, D, D);
    launch_gemm(enc_qry, WATT(3,2), BATT(3,2), nullptr,1,0, vb, 512, D, D);
    launch_attn(qb, kb, vb, ob, qry_mask, 1, 1, BSZ, TTRG, 32, 1, 32, 1, 1);
    launch_gemm(ob, WATT(3,3), BATT(3,3), cur, 64, 0, cur, NT, D, D);
    // cur == mm from here on (not modified again)

    // ===== temporal2spatial: MHA4 over T per spatial location =====
    ln_kernel<<<NT,256>>>(cur, ln_g + 4*D, ln_b + 4*D, lnb);
    launch_gemm(lnb, WATT(4,0), BATT(4,0), nullptr,1,0, qb,   NT, D, D);
    launch_gemm(vft, WATT(4,1), BATT(4,1), nullptr,1,0, big0, NV, D, D);   // K4 [b,t,s]
    launch_gemm(vft, WATT(4,2), BATT(4,2), nullptr,1,0, big1, NV, D, D);   // V4
    // batch unit i=b*S+s; keys tk over T at row b*T*S + tk*S + s
    launch_attn(qb, big0, big1, big2, tmp_mask, 1, SSP,
                BSZ*SSP, TTRG, TT, SSP, TT*SSP, SSP, SSP);
    // t_out = mm(bcast) + O4 @ Wo
    launch_gemm(big2, WATT(4,3), BATT(4,3), cur, SSP*TTRG, 0, big3, NV, D, D);

    // ===== MHA5: 1 query over S (p_t) =====
    ln_kernel<<<NT,256>>>(cur, ln_g + 5*D, ln_b + 5*D, lnb);
    launch_gemm(lnb,  WATT(5,0), BATT(5,0), nullptr,1,0, qb,   NT, D, D);
    launch_gemm(big3, WATT(5,1), BATT(5,1), nullptr,1,0, big0, NV, D, D);  // K5 [b,s,tq]
    launch_gemm(big3, WATT(5,2), BATT(5,2), nullptr,1,0, big1, NV, D, D);  // V5
    // i=b*Ttrg+tq; keys s at row b*S*Ttrg + s*Ttrg + tq
    launch_attn(qb, big0, big1, ob, nullptr, 0, 1,
                NT, 1, SSP, 1, SSP*TTRG, TTRG, TTRG);
    launch_gemm(ob, WATT(5,3), BATT(5,3), cur, 64, 0, ts, NT, D, D);

    // ===== FFN0 on ts =====
    ln_kernel<<<NT,256>>>(ts, ln_g + 6*D, ln_b + 6*D, lnb);
    launch_gemm(lnb, ff_w1 + 0*(size_t)D*DFF, ff_b1 + 0*DFF, nullptr,1,1, mid, NT, DFF, D);
    launch_gemm(mid, ff_w2 + 0*(size_t)DFF*D, ff_b2 + 0*D,   ts, 64, 0,   ts,  NT, D, DFF);

    // ===== spatial2temporal: MHA6 over S per frame (attn_w[6], ln 7) =====
    ln_kernel<<<NT,256>>>(cur, ln_g + 7*D, ln_b + 7*D, lnb);
    launch_gemm(lnb, WATT(6,0), BATT(6,0), nullptr,1,0, qb,   NT, D, D);
    launch_gemm(vft, WATT(6,1), BATT(6,1), nullptr,1,0, big0, NV, D, D);   // K6 [b,t,s]
    launch_gemm(vft, WATT(6,2), BATT(6,2), nullptr,1,0, big1, NV, D, D);   // V6
    // i=b*T+t; keys s at row (b*T+t)*S + s
    launch_attn(qb, big0, big1, big2, nullptr, 0, 1,
                BSZ*TT, TTRG, SSP, TT, SSP, 1, 1);
    // s_out = mm(bcast) + O6 @ Wo   [b,t,tq]
    launch_gemm(big2, WATT(6,3), BATT(6,3), cur, TT*TTRG, 0, big3, NBIG, D, D);

    // ===== MHA7: 1 query over T (p_s) (attn_w[7], ln 8) =====
    ln_kernel<<<NT,256>>>(cur, ln_g + 8*D, ln_b + 8*D, lnb);
    launch_gemm(lnb,  WATT(7,0), BATT(7,0), nullptr,1,0, qb,   NT,   D, D);
    launch_gemm(big3, WATT(7,1), BATT(7,1), nullptr,1,0, big0, NBIG, D, D); // K7 [b,t,tq]
    launch_gemm(big3, WATT(7,2), BATT(7,2), nullptr,1,0, big1, NBIG, D, D); // V7
    // i=b*Ttrg+tq; keys t at row b*T*Ttrg + t*Ttrg + tq; temporal mask
    launch_attn(qb, big0, big1, ob, tmp_mask, 1, TTRG,
                NT, 1, TT, 1, TT*TTRG, TTRG, TTRG);
    launch_gemm(ob, WATT(7,3), BATT(7,3), cur, 64, 0, st, NT, D, D);

    // ===== FFN1 on st =====
    ln_kernel<<<NT,256>>>(st, ln_g + 9*D, ln_b + 9*D, lnb);
    launch_gemm(lnb, ff_w1 + 1*(size_t)D*DFF, ff_b1 + 1*DFF, nullptr,1,1, mid, NT, DFF, D);
    launch_gemm(mid, ff_w2 + 1*(size_t)DFF*D, ff_b2 + 1*D,   st, 64, 0,   st,  NT, D, DFF);

    // ===== out = ts + st; FFN2 =====
    add_kernel<<<(NT*D+255)/256,256>>>(ts, st, qb, NT*D);   // qb reused as sum
    ln_kernel<<<NT,256>>>(qb, ln_g + 10*D, ln_b + 10*D, lnb);
    launch_gemm(lnb, ff_w1 + 2*(size_t)D*DFF, ff_b1 + 2*DFF, nullptr,1,1, mid, NT, DFF, D);
    launch_gemm(mid, ff_w2 + 2*(size_t)DFF*D, ff_b2 + 2*D,   qb, 64, 0,   outp, NT, D, DFF);
}

// round 3
// speedup vs baseline: 1.4239x; 1.4239x over previous
#include <cuda_runtime.h>
#include <math.h>
#include <stdint.h>

// ---------------- constants ----------------
#define D     512
#define NH    8
#define DK    64
#define BSZ   16
#define TTRG  64
#define TT    64
#define SSP   49
#define DFF   2048
#define NT    1024      /* B*Ttrg */
#define NV    50176     /* B*T*S  */
#define NBIG  65536     /* B*T*Ttrg */

// ---------------- scratch (device globals; allocation-free) ----------------
__device__ float g_big0[(size_t)NV * D];     // K (vft proj)
__device__ float g_big1[(size_t)NV * D];     // V (vft proj)
__device__ float g_big2[(size_t)NV * D];     // O4
__device__ float g_big3[(size_t)NBIG * D];   // O6
__device__ float g_ln [(size_t)NT * D];
__device__ float g_q  [(size_t)NT * D];      // Qp
__device__ float g_o  [(size_t)NT * D];      // attn_out
__device__ float g_cur[(size_t)NT * D];
__device__ float g_ts [(size_t)NT * D];
__device__ float g_st [(size_t)NT * D];
__device__ float g_k  [(size_t)2048 * D];
__device__ float g_v  [(size_t)2048 * D];
__device__ float g_mid[(size_t)NT * DFF];
__device__ float g_mmb[(size_t)NT * D];
__device__ float g_mmk[(size_t)NT * D];
__device__ float g_mmv[(size_t)NT * D];
__device__ float g_sb [(size_t)NT * NH];
__device__ float g_qo [(size_t)NT * NH * D]; // [u][h][512]
__device__ float g_ctx[(size_t)NT * NH * D];
__device__ float g_w1 [(size_t)D * D];       // WoWk
__device__ float g_w1t[(size_t)D * D];       // (WoWk)^T
__device__ float g_w2 [(size_t)D * D];       // WoWv

// ---------------- SGEMM: C = A@W + bias (+res) (+relu), strided -----------
template<int BM,int BN,int BK,int TM,int TN>
__global__ void sgemm_kernel(int M, int N, int K,
                             const float* __restrict__ A, int lda,
                             const float* __restrict__ W, int ldb,
                             const float* __restrict__ bias,
                             const float* res, int ldres, int relu,
                             float* C, int ldc)
{
    constexpr int THREADS = (BM/TM)*(BN/TN);
    __shared__ float As[BK][BM];
    __shared__ float Bs[BK][BN];
    const int tid = threadIdx.x;
    const int bm = blockIdx.y * BM;
    const int bn = blockIdx.x * BN;
    const int tc = tid % (BN/TN);
    const int tr = tid / (BN/TN);

    float acc[TM][TN];
    #pragma unroll
    for (int i=0;i<TM;i++)
        #pragma unroll
        for (int j=0;j<TN;j++) acc[i][j] = 0.f;

    constexpr int A_F4 = (BM*BK)/(4*THREADS);
    constexpr int B_F4 = (BK*BN)/(4*THREADS);

    for (int k0 = 0; k0 < K; k0 += BK) {
        #pragma unroll
        for (int t = 0; t < A_F4; t++) {
            int idx = tid + t*THREADS;
            int row = idx / (BK/4);
            int kq  = idx % (BK/4);
            float4 v = *(const float4*)(A + (size_t)(bm+row)*lda + k0 + kq*4);
            As[kq*4+0][row] = v.x;
            As[kq*4+1][row] = v.y;
            As[kq*4+2][row] = v.z;
            As[kq*4+3][row] = v.w;
        }
        #pragma unroll
        for (int t = 0; t < B_F4; t++) {
            int idx = tid + t*THREADS;
            int kr = idx / (BN/4);
            int nq = idx % (BN/4);
            float4 v = *(const float4*)(W + (size_t)(k0+kr)*ldb + bn + nq*4);
            *(float4*)&Bs[kr][nq*4] = v;
        }
        __syncthreads();
        #pragma unroll
        for (int kk = 0; kk < BK; kk++) {
            float ra[TM], rb[TN];
            #pragma unroll
            for (int i=0;i<TM;i++) ra[i] = As[kk][tr*TM+i];
            #pragma unroll
            for (int j=0;j<TN;j++) rb[j] = Bs[kk][tc*TN+j];
            #pragma unroll
            for (int i=0;i<TM;i++)
                #pragma unroll
                for (int j=0;j<TN;j++) acc[i][j] += ra[i]*rb[j];
        }
        __syncthreads();
    }

    #pragma unroll
    for (int i=0;i<TM;i++) {
        int row = bm + tr*TM + i;
        #pragma unroll
        for (int j=0;j<TN;j++) {
            int col = bn + tc*TN + j;
            float v = acc[i][j];
            if (bias) v += bias[col];
            if (res)  v += res[(size_t)row*ldres + col];
            if (relu) v = fmaxf(v, 0.f);
            C[(size_t)row*ldc + col] = v;
        }
    }
}

static void launch_gemm(const float* A, int lda, const float* W, int ldb,
                        const float* bias, const float* res, int ldres, int relu,
                        float* C, int ldc, int M, int N, int K)
{
    if (M >= 8192 && (M % 128) == 0 && (N % 128) == 0) {
        dim3 grid(N/128, M/128);
        sgemm_kernel<128,128,16,8,8><<<grid,256>>>(M,N,K,A,lda,W,ldb,bias,res,ldres,relu,C,ldc);
    } else {
        dim3 grid(N/64, M/64);
        sgemm_kernel<64,64,16,4,4><<<grid,256>>>(M,N,K,A,lda,W,ldb,bias,res,ldres,relu,C,ldc);
    }
}

// ---------------- LayerNorm (row = 512 elems) --------------------------
__global__ void ln_kernel(const float* __restrict__ X,
                          const float* __restrict__ g,
                          const float* __restrict__ b,
                          float* __restrict__ Y)
{
    const int row = blockIdx.x;
    const int tid = threadIdx.x;
    const float* x = X + (size_t)row * D;
    float v0 = x[tid], v1 = x[tid+256];
    __shared__ float red[16];

    float s = v0 + v1;
    #pragma unroll
    for (int o=16;o>0;o>>=1) s += __shfl_xor_sync(0xffffffffu, s, o);
    if ((tid & 31) == 0) red[tid>>5] = s;
    __syncthreads();
    if (tid < 32) {
        float t = (tid < 8) ? red[tid] : 0.f;
        #pragma unroll
        for (int o=4;o>0;o>>=1) t += __shfl_xor_sync(0xffffffffu, t, o);
        if (tid == 0) red[8] = t;
    }
    __syncthreads();
    const float mean = red[8] * (1.f/512.f);
    const float d0 = v0 - mean, d1 = v1 - mean;
    s = d0*d0 + d1*d1;
    #pragma unroll
    for (int o=16;o>0;o>>=1) s += __shfl_xor_sync(0xffffffffu, s, o);
    if ((tid & 31) == 0) red[tid>>5] = s;
    __syncthreads();
    if (tid < 32) {
        float t = (tid < 8) ? red[tid] : 0.f;
        #pragma unroll
        for (int o=4;o>0;o>>=1) t += __shfl_xor_sync(0xffffffffu, t, o);
        if (tid == 0) red[9] = t;
    }
    __syncthreads();
    const float stdv = sqrtf(red[9] * (1.f/512.f));
    const float inv = 1.f / (stdv + 1e-6f);
    Y[(size_t)row*D + tid      ] = g[tid]     * d0 * inv + b[tid];
    Y[(size_t)row*D + tid + 256] = g[tid+256] * d1 * inv + b[tid+256];
}

// ---------------- generic strided attention ----------------------------
__global__ void attn_kernel(const float* __restrict__ Q,
                            const float* __restrict__ K,
                            const float* __restrict__ V,
                            float* __restrict__ O,
                            const int* __restrict__ mask,
                            int maskMode, int maskDiv,
                            int Lq, int Lk,
                            int qDiv, int kOuter, int kDiv, int kStride,
                            float scale)
{
    extern __shared__ float sm[];
    float* Ks = sm;
    float* Vs = Ks + Lk*65;
    float* qs = Vs + Lk*65;
    float* ps = qs + 4*64;

    const int i = blockIdx.x;
    const int h = blockIdx.y;
    const int tid = threadIdx.x;
    const int lane = tid & 31;
    const int w = tid >> 5;

    const size_t kBase = (size_t)(i/kDiv)*kOuter + (size_t)(i%kDiv);

    for (int idx = tid; idx < Lk*64; idx += 128) {
        int tk = idx >> 6, d = idx & 63;
        size_t grow = (kBase + (size_t)tk*kStride)*D + h*DK + d;
        Ks[tk*65+d] = K[grow];
        Vs[tk*65+d] = V[grow];
    }
    __syncthreads();

    const int qb = (i/qDiv) * Lq;
    const int nj = (Lk + 31) >> 5;

    for (int tq = w; tq < Lq; tq += 4) {
        size_t qoff = (size_t)(qb + tq)*D + h*DK;
        qs[w*64 + lane]      = Q[qoff + lane];
        qs[w*64 + lane + 32] = Q[qoff + lane + 32];
        __syncwarp();

        float sc[4];
        #pragma unroll
        for (int j=0;j<4;j++) sc[j] = -INFINITY;

        for (int j=0;j<nj;j++) {
            int k = lane + (j<<5);
            if (k < Lk) {
                float dot = 0.f;
                const float* kr = Ks + k*65;
                const float* qq = qs + w*64;
                #pragma unroll
                for (int d=0; d<64; d++) dot += qq[d]*kr[d];
                dot *= scale;
                if (maskMode == 1) {
                    if (mask[(size_t)(i/maskDiv)*Lk + k] == 0) dot = -1e9f;
                } else if (maskMode == 2) {
                    if (mask[((size_t)i*Lq + tq)*Lk + k] == 0) dot = -1e9f;
                }
                sc[j] = dot;
            }
        }
        float mx = -INFINITY;
        for (int j=0;j<nj;j++) mx = fmaxf(mx, sc[j]);
        #pragma unroll
        for (int o=16;o>0;o>>=1) mx = fmaxf(mx, __shfl_xor_sync(0xffffffffu, mx, o));

        float e[4]; float sum = 0.f;
        for (int j=0;j<nj;j++) {
            e[j] = (sc[j] == -INFINITY) ? 0.f : __expf(sc[j] - mx);
            sum += e[j];
        }
        #pragma unroll
        for (int o=16;o>0;o>>=1) sum += __shfl_xor_sync(0xffffffffu, sum, o);
        const float inv = 1.f / sum;
        for (int j=0;j<nj;j++) {
            int k = lane + (j<<5);
            if (k < Lk) ps[w*Lk + k] = e[j] * inv;
        }
        __syncwarp();

        float o0 = 0.f, o1 = 0.f;
        for (int k=0;k<Lk;k++) {
            float p = ps[w*Lk + k];
            o0 += p * Vs[k*65 + lane];
            o1 += p * Vs[k*65 + lane + 32];
        }
        size_t orow = ((size_t)i*Lq + tq)*D + h*DK;
        O[orow + lane]      = o0;
        O[orow + lane + 32] = o1;
        __syncwarp();
    }
}

static void launch_attn(const float* Q, const float* K, const float* V, float* O,
                        const int* mask, int maskMode, int maskDiv,
                        int nb, int Lq, int Lk,
                        int qDiv, int kOuter, int kDiv, int kStride)
{
    dim3 grid(nb, NH);
    size_t smem = (size_t)(2*Lk*65 + 4*64 + 4*Lk) * sizeof(float);
    attn_kernel<<<grid, 128, smem>>>(Q, K, V, O, mask, maskMode, maskDiv,
                                     Lq, Lk, qDiv, kOuter, kDiv, kStride, 0.125f);
}

// ---------------- fold attention (Lq=1 per unit; K/V folded) ------------
// unit u = b*64 + tq ; key s -> O row = (u>>6)*Lk*64 + s*64 + (u&63)
// score(h,s) = (sbase[u,h] + Qo[u,h,:]·O_row) * 0.125, optional mask[(u>>6)*Lk+s]
// ctx[u,h,:] = sum_s softmax(score)_s * O_row
__global__ void fold_attn_kernel(const float* __restrict__ O,
                                 const float* __restrict__ Qo,
                                 const float* __restrict__ sb,
                                 const int* __restrict__ mask, int maskApply,
                                 float* __restrict__ ctx, int Lk)
{
    extern __shared__ float sm[];
    float* Os = sm;               // Lk*512
    float* sc = Os + Lk*512;      // 8*64
    float* pp = sc + 512;         // 8*64

    const int u = blockIdx.x;
    const int tid = threadIdx.x;
    const int h = tid >> 5;
    const int lane = tid & 31;
    const size_t base = (size_t)(u >> 6) * Lk * 64 + (u & 63);

    for (int idx = tid; idx < Lk*512; idx += 256) {
        int s = idx >> 9, d = idx & 511;
        Os[idx] = O[(base + (size_t)s*64)*D + d];
    }
    __syncthreads();

    float qreg[16];
    #pragma unroll
    for (int i=0;i<16;i++) qreg[i] = Qo[(size_t)u*(NH*D) + h*D + i*32 + lane];

    const float sbase = sb[u*NH + h];

    for (int s = 0; s < Lk; s++) {
        float dot = 0.f;
        const float* row = Os + s*512;
        #pragma unroll
        for (int i=0;i<16;i++) dot += qreg[i] * row[i*32 + lane];
        #pragma unroll
        for (int o=16;o>0;o>>=1) dot += __shfl_xor_sync(0xffffffffu, dot, o);
        float score = (sbase + dot) * 0.125f;
        if (maskApply && mask[(u>>6)*Lk + s] == 0) score = -1e9f;
        if (lane == 0) sc[h*64 + s] = score;
    }
    __syncwarp();

    // softmax over Lk (per warp/head)
    float v0 = (lane      < Lk) ? sc[h*64 + lane]      : -INFINITY;
    float v1 = (lane + 32 < Lk) ? sc[h*64 + lane + 32] : -INFINITY;
    float mx = fmaxf(v0, v1);
    #pragma unroll
    for (int o=16;o>0;o>>=1) mx = fmaxf(mx, __shfl_xor_sync(0xffffffffu, mx, o));
    float e0 = (lane      < Lk) ? __expf(v0 - mx) : 0.f;
    float e1 = (lane + 32 < Lk) ? __expf(v1 - mx) : 0.f;
    float sum = e0 + e1;
    #pragma unroll
    for (int o=16;o>0;o>>=1) sum += __shfl_xor_sync(0xffffffffu, sum, o);
    const float inv = 1.f / sum;
    if (lane      < Lk) pp[h*64 + lane]      = e0 * inv;
    if (lane + 32 < Lk) pp[h*64 + lane + 32] = e1 * inv;
    __syncwarp();

    #pragma unroll
    for (int i=0;i<16;i++) {
        float acc = 0.f;
        for (int s=0;s<Lk;s++)
            acc += pp[h*64 + s] * Os[s*512 + i*32 + lane];
        ctx[(size_t)u*(NH*D) + h*D + i*32 + lane] = acc;
    }
}

// ---------------- small helpers ----------------
__global__ void transpose512(const float* __restrict__ in, float* __restrict__ out)
{
    __shared__ float t[32][33];
    int bx = blockIdx.x*32, by = blockIdx.y*32;
    for (int j = threadIdx.y; j < 32; j += 8)
        t[j][threadIdx.x] = in[(size_t)(by+j)*D + bx + threadIdx.x];
    __syncthreads();
    for (int j = threadIdx.y; j < 32; j += 8)
        out[(size_t)(bx+j)*D + by + threadIdx.x] = t[threadIdx.x][j];
}

__global__ void addrow_kernel(const float* __restrict__ a, const float* __restrict__ bvec,
                              float* __restrict__ c)
{
    int u = blockIdx.x, d = threadIdx.x;
    c[(size_t)u*D + d] = a[(size_t)u*D + d] + bvec[d];
}

// sbase[u,h] = sum_{j<64} Qp[u,h*64+j] * mmk[u,h*64+j]
__global__ void sbase_kernel(const float* __restrict__ Qp, const float* __restrict__ mmk,
                             float* __restrict__ sb)
{
    int u = blockIdx.x;
    int h = threadIdx.x >> 5, lane = threadIdx.x & 31;
    const float* q = Qp  + (size_t)u*D + h*64;
    const float* m = mmk + (size_t)u*D + h*64;
    float s = q[lane]*m[lane] + q[lane+32]*m[lane+32];
    #pragma unroll
    for (int o=16;o>0;o>>=1) s += __shfl_xor_sync(0xffffffffu, s, o);
    if (lane == 0) sb[u*NH + h] = s;
}

__global__ void add_kernel(const float* __restrict__ a, const float* __restrict__ b,
                           float* __restrict__ c, int n)
{
    int i = blockIdx.x*256 + threadIdx.x;
    if (i < n) c[i] = a[i] + b[i];
}

// ---------------- driver ----------------
extern "C" void kernel_launch(void* const* d_in, const int* in_sizes, int n_in,
                              void* d_out, int out_size)
{
    const float* x        = (const float*)d_in[0];
    const float* vft      = (const float*)d_in[1];
    const float* enc_his  = (const float*)d_in[2];
    const float* enc_cap  = (const float*)d_in[3];
    const float* enc_qry  = (const float*)d_in[4];
    const int*   trg_mask = (const int*)  d_in[5];
    const int*   his_mask = (const int*)  d_in[6];
    const int*   cap_mask = (const int*)  d_in[7];
    const int*   qry_mask = (const int*)  d_in[8];
    const int*   tmp_mask = (const int*)  d_in[9];
    const float* attn_w   = (const float*)d_in[10];
    const float* attn_b   = (const float*)d_in[11];
    const float* ff_w1    = (const float*)d_in[12];
    const float* ff_b1    = (const float*)d_in[13];
    const float* ff_w2    = (const float*)d_in[14];
    const float* ff_b2    = (const float*)d_in[15];
    const float* ln_g     = (const float*)d_in[16];
    const float* ln_b     = (const float*)d_in[17];
    float* outp = (float*)d_out;

    float *big0,*big1,*big2,*big3,*lnb,*qb,*ob,*cur,*ts,*st,*kb,*vb,*mid;
    float *mmb,*mmk,*mmv,*sb,*qo,*ctx,*w1,*w1t,*w2;
    cudaGetSymbolAddress((void**)&big0, g_big0);
    cudaGetSymbolAddress((void**)&big1, g_big1);
    cudaGetSymbolAddress((void**)&big2, g_big2);
    cudaGetSymbolAddress((void**)&big3, g_big3);
    cudaGetSymbolAddress((void**)&lnb,  g_ln);
    cudaGetSymbolAddress((void**)&qb,   g_q);
    cudaGetSymbolAddress((void**)&ob,   g_o);
    cudaGetSymbolAddress((void**)&cur,  g_cur);
    cudaGetSymbolAddress((void**)&ts,   g_ts);
    cudaGetSymbolAddress((void**)&st,   g_st);
    cudaGetSymbolAddress((void**)&kb,   g_k);
    cudaGetSymbolAddress((void**)&vb,   g_v);
    cudaGetSymbolAddress((void**)&mid,  g_mid);
    cudaGetSymbolAddress((void**)&mmb,  g_mmb);
    cudaGetSymbolAddress((void**)&mmk,  g_mmk);
    cudaGetSymbolAddress((void**)&mmv,  g_mmv);
    cudaGetSymbolAddress((void**)&sb,   g_sb);
    cudaGetSymbolAddress((void**)&qo,   g_qo);
    cudaGetSymbolAddress((void**)&ctx,  g_ctx);
    cudaGetSymbolAddress((void**)&w1,   g_w1);
    cudaGetSymbolAddress((void**)&w1t,  g_w1t);
    cudaGetSymbolAddress((void**)&w2,   g_w2);

    cudaFuncSetAttribute(attn_kernel, cudaFuncAttributeMaxDynamicSharedMemorySize, 73728);
    cudaFuncSetAttribute(fold_attn_kernel, cudaFuncAttributeMaxDynamicSharedMemorySize, 64*512*4 + 4096);

    #define WATT(l,j) (attn_w + ((size_t)(l)*4+(j))*D*D)
    #define BATT(l,j) (attn_b + ((size_t)(l)*4+(j))*D)

    // ===== MHA0: self-attn, causal mask =====
    ln_kernel<<<NT,256>>>(x, ln_g + 0*D, ln_b + 0*D, lnb);
    launch_gemm(lnb,D, WATT(0,0),D, BATT(0,0), nullptr,0,0, qb,D, NT, D, D);
    launch_gemm(lnb,D, WATT(0,1),D, BATT(0,1), nullptr,0,0, kb,D, NT, D, D);
    launch_gemm(lnb,D, WATT(0,2),D, BATT(0,2), nullptr,0,0, vb,D, NT, D, D);
    launch_attn(qb, kb, vb, ob, trg_mask, 2, 1, BSZ, TTRG, TTRG, 1, TTRG, 1, 1);
    launch_gemm(ob,D, WATT(0,3),D, BATT(0,3), x,D,0, cur,D, NT, D, D);

    // ===== MHA1: cross-attn encoded_his (Lk=128) =====
    ln_kernel<<<NT,256>>>(cur, ln_g + 1*D, ln_b + 1*D, lnb);
    launch_gemm(lnb,D,     WATT(1,0),D, BATT(1,0), nullptr,0,0, qb,D, NT,   D, D);
    launch_gemm(enc_his,D, WATT(1,1),D, BATT(1,1), nullptr,0,0, kb,D, 2048, D, D);
    launch_gemm(enc_his,D, WATT(1,2),D, BATT(1,2), nullptr,0,0, vb,D, 2048, D, D);
    launch_attn(qb, kb, vb, ob, his_mask, 1, 1, BSZ, TTRG, 128, 1, 128, 1, 1);
    launch_gemm(ob,D, WATT(1,3),D, BATT(1,3), cur,D,0, cur,D, NT, D, D);

    // ===== MHA2: cross-attn encoded_cap (Lk=64) =====
    ln_kernel<<<NT,256>>>(cur, ln_g + 2*D, ln_b + 2*D, lnb);
    launch_gemm(lnb,D,     WATT(2,0),D, BATT(2,0), nullptr,0,0, qb,D, NT,   D, D);
    launch_gemm(enc_cap,D, WATT(2,1),D, BATT(2,1), nullptr,0,0, kb,D, 1024, D, D);
    launch_gemm(enc_cap,D, WATT(2,2),D, BATT(2,2), nullptr,0,0, vb,D, 1024, D, D);
    launch_attn(qb, kb, vb, ob, cap_mask, 1, 1, BSZ, TTRG, 64, 1, 64, 1, 1);
    launch_gemm(ob,D, WATT(2,3),D, BATT(2,3), cur,D,0, cur,D, NT, D, D);

    // ===== MHA3: cross-attn encoded_query (Lk=32) -> mm (cur) =====
    ln_kernel<<<NT,256>>>(cur, ln_g + 3*D, ln_b + 3*D, lnb);
    launch_gemm(lnb,D,     WATT(3,0),D, BATT(3,0), nullptr,0,0, qb,D, NT,  D, D);
    launch_gemm(enc_qry,D, WATT(3,1),D, BATT(3,1), nullptr,0,0, kb,D, 512, D, D);
    launch_gemm(enc_qry,D, WATT(3,2),D, BATT(3,2), nullptr,0,0, vb,D, 512, D, D);
    launch_attn(qb, kb, vb, ob, qry_mask, 1, 1, BSZ, TTRG, 32, 1, 32, 1, 1);
    launch_gemm(ob,D, WATT(3,3),D, BATT(3,3), cur,D,0, cur,D, NT, D, D);
    // cur == mm from here on

    // ===== temporal2spatial: MHA4 over T per spatial location =====
    ln_kernel<<<NT,256>>>(cur, ln_g + 4*D, ln_b + 4*D, lnb);
    launch_gemm(lnb,D, WATT(4,0),D, BATT(4,0), nullptr,0,0, qb,D,   NT, D, D);
    launch_gemm(vft,D, WATT(4,1),D, BATT(4,1), nullptr,0,0, big0,D, NV, D, D);   // K4
    launch_gemm(vft,D, WATT(4,2),D, BATT(4,2), nullptr,0,0, big1,D, NV, D, D);   // V4
    launch_attn(qb, big0, big1, big2, tmp_mask, 1, SSP,
                BSZ*SSP, TTRG, TT, SSP, TT*SSP, SSP, SSP);                       // O4

    // ===== MHA5 (folded): 1 query over S; K/V = mm_bcast + O4@Wo4 =====
    {
        const float* Wo = WATT(4,3); const float* bo = BATT(4,3);
        const float* Wq = WATT(5,0), *Wk = WATT(5,1), *Wv = WATT(5,2), *Wo5 = WATT(5,3);
        addrow_kernel<<<NT,512>>>(cur, bo, mmb);
        launch_gemm(mmb,D, Wk,D, BATT(5,1), nullptr,0,0, mmk,D, NT, D, D);
        launch_gemm(mmb,D, Wv,D, BATT(5,2), nullptr,0,0, mmv,D, NT, D, D);
        ln_kernel<<<NT,256>>>(cur, ln_g + 5*D, ln_b + 5*D, lnb);
        launch_gemm(lnb,D, Wq,D, BATT(5,0), nullptr,0,0, qb,D, NT, D, D);        // Qp
        launch_gemm(Wo,D, Wk,D, nullptr, nullptr,0,0, w1,D, D, D, D);            // WoWk
        transpose512<<<dim3(16,16),dim3(32,8)>>>(w1, w1t);
        launch_gemm(Wo,D, Wv,D, nullptr, nullptr,0,0, w2,D, D, D, D);            // WoWv
        for (int h=0; h<NH; h++)                                                  // Qo_h
            launch_gemm(qb + h*64, D, w1t + (size_t)h*64*D, D, nullptr, nullptr,0,0,
                        qo + h*D, NH*D, NT, D, 64);
        sbase_kernel<<<NT,256>>>(qb, mmk, sb);
        fold_attn_kernel<<<NT,256, SSP*512*4 + 4096>>>(big2, qo, sb, nullptr, 0, ctx, SSP);
        for (int h=0; h<NH; h++)                                                  // attn_out slice
            launch_gemm(ctx + h*D, NH*D, w2 + h*64, D, nullptr, mmv + h*64, D, 0,
                        ob + h*64, D, NT, 64, D);
        launch_gemm(ob,D, Wo5,D, BATT(5,3), cur,D,0, ts,D, NT, D, D);
    }

    // ===== FFN0 on ts =====
    ln_kernel<<<NT,256>>>(ts, ln_g + 6*D, ln_b + 6*D, lnb);
    launch_gemm(lnb,D, ff_w1 + 0*(size_t)D*DFF,DFF, ff_b1 + 0*DFF, nullptr,0,1, mid,DFF, NT, DFF, D);
    launch_gemm(mid,DFF, ff_w2 + 0*(size_t)DFF*D,D, ff_b2 + 0*D, ts,D,0, ts,D, NT, D, DFF);

    // ===== spatial2temporal: MHA6 over S per frame =====
    ln_kernel<<<NT,256>>>(cur, ln_g + 7*D, ln_b + 7*D, lnb);
    launch_gemm(lnb,D, WATT(6,0),D, BATT(6,0), nullptr,0,0, qb,D,   NT, D, D);
    launch_gemm(vft,D, WATT(6,1),D, BATT(6,1), nullptr,0,0, big0,D, NV, D, D);   // K6
    launch_gemm(vft,D, WATT(6,2),D, BATT(6,2), nullptr,0,0, big1,D, NV, D, D);   // V6
    launch_attn(qb, big0, big1, big3, nullptr, 0, 1,
                BSZ*TT, TTRG, SSP, TT, SSP, 1, 1);                               // O6

    // ===== MHA7 (folded): 1 query over T; K/V = mm_bcast + O6@Wo6; temporal mask =====
    {
        const float* Wo = WATT(6,3); const float* bo = BATT(6,3);
        const float* Wq = WATT(7,0), *Wk = WATT(7,1), *Wv = WATT(7,2), *Wo7 = WATT(7,3);
        addrow_kernel<<<NT,512>>>(cur, bo, mmb);
        launch_gemm(mmb,D, Wk,D, BATT(7,1), nullptr,0,0, mmk,D, NT, D, D);
        launch_gemm(mmb,D, Wv,D, BATT(7,2), nullptr,0,0, mmv,D, NT, D, D);
        ln_kernel<<<NT,256>>>(cur, ln_g + 8*D, ln_b + 8*D, lnb);
        launch_gemm(lnb,D, Wq,D, BATT(7,0), nullptr,0,0, qb,D, NT, D, D);
        launch_gemm(Wo,D, Wk,D, nullptr, nullptr,0,0, w1,D, D, D, D);
        transpose512<<<dim3(16,16),dim3(32,8)>>>(w1, w1t);
        launch_gemm(Wo,D, Wv,D, nullptr, nullptr,0,0, w2,D, D, D, D);
        for (int h=0; h<NH; h++)
            launch_gemm(qb + h*64, D, w1t + (size_t)h*64*D, D, nullptr, nullptr,0,0,
                        qo + h*D, NH*D, NT, D, 64);
        sbase_kernel<<<NT,256>>>(qb, mmk, sb);
        fold_attn_kernel<<<NT,256, TT*512*4 + 4096>>>(big3, qo, sb, tmp_mask, 1, ctx, TT);
        for (int h=0; h<NH; h++)
            launch_gemm(ctx + h*D, NH*D, w2 + h*64, D, nullptr, mmv + h*64, D, 0,
                        ob + h*64, D, NT, 64, D);
        launch_gemm(ob,D, Wo7,D, BATT(7,3), cur,D,0, st,D, NT, D, D);
    }

    // ===== FFN1 on st =====
    ln_kernel<<<NT,256>>>(st, ln_g + 9*D, ln_b + 9*D, lnb);
    launch_gemm(lnb,D, ff_w1 + 1*(size_t)D*DFF,DFF, ff_b1 + 1*DFF, nullptr,0,1, mid,DFF, NT, DFF, D);
    launch_gemm(mid,DFF, ff_w2 + 1*(size_t)DFF*D,D, ff_b2 + 1*D, st,D,0, st,D, NT, D, DFF);

    // ===== out = ts + st; FFN2 =====
    add_kernel<<<(NT*D+255)/256,256>>>(ts, st, qb, NT*D);
    ln_kernel<<<NT,256>>>(qb, ln_g + 10*D, ln_b + 10*D, lnb);
    launch_gemm(lnb,D, ff_w1 + 2*(size_t)D*DFF,DFF, ff_b1 + 2*DFF, nullptr,0,1, mid,DFF, NT, DFF, D);
    launch_gemm(mid,DFF, ff_w2 + 2*(size_t)DFF*D,D, ff_b2 + 2*D, qb,D,0, outp,D, NT, D, DFF);
}

// round 4
// speedup vs baseline: 1.6706x; 1.1732x over previous
#include <cuda_runtime.h>
#include <math.h>
#include <stdint.h>
#include <mma.h>
using namespace nvcuda;

// ---------------- constants ----------------
#define D     512
#define NH    8
#define DK    64
#define BSZ   16
#define TTRG  64
#define TT    64
#define SSP   49
#define DFF   2048
#define NT    1024      /* B*Ttrg */
#define NV    50176     /* B*T*S  */
#define NBIG  65536     /* B*T*Ttrg */

// ---------------- scratch (device globals; allocation-free) ----------------
__device__ float g_big0[(size_t)NV * D];     // K (vft proj)
__device__ float g_big1[(size_t)NV * D];     // V (vft proj)
__device__ float g_big2[(size_t)NV * D];     // O4
__device__ float g_big3[(size_t)NBIG * D];   // O6
__device__ float g_ln [(size_t)NT * D];
__device__ float g_q  [(size_t)NT * D];      // Qp
__device__ float g_o  [(size_t)NT * D];      // attn_out
__device__ float g_cur[(size_t)NT * D];
__device__ float g_ts [(size_t)NT * D];
__device__ float g_st [(size_t)NT * D];
__device__ float g_k  [(size_t)2048 * D];
__device__ float g_v  [(size_t)2048 * D];
__device__ float g_mid[(size_t)NT * DFF];
__device__ float g_mmb[(size_t)NT * D];
__device__ float g_mmk[(size_t)NT * D];
__device__ float g_mmv[(size_t)NT * D];
__device__ float g_sb [(size_t)NT * NH];
__device__ float g_qo [(size_t)NT * NH * D]; // [u][h][512]
__device__ float g_ctx[(size_t)NT * NH * D];
__device__ float g_w1 [(size_t)D * D];       // WoWk
__device__ float g_w1t[(size_t)D * D];       // (WoWk)^T
__device__ float g_w2 [(size_t)D * D];       // WoWv

// ---------------- tf32 WMMA GEMM: C = A@W + bias (big M only) -------------
// BM=64, BN=64, BK=16, 4 warps (128 threads); each warp 32x32 via 2x2 wmma.
__global__ void tf32_gemm_kernel(int M, int N, int K,
                                 const float* __restrict__ A, int lda,
                                 const float* __restrict__ W, int ldb,
                                 const float* __restrict__ bias,
                                 float* __restrict__ C, int ldc)
{
    __shared__ float smem[64*68];        // reused: (As[64][20] + Bs[16][68]) then Cs[64][68]
    float* As = smem;                    // [64][20]
    float* Bs = smem + 64*20;            // [16][68]
    const int tid = threadIdx.x;
    const int wid = tid >> 5;
    const int wm = wid >> 1;             // 0..1
    const int wn = wid & 1;              // 0..1
    const int bm = blockIdx.y * 64;
    const int bn = blockIdx.x * 64;

    wmma::fragment<wmma::accumulator, 16,16,8, float> c[2][2];
    #pragma unroll
    for (int i=0;i<2;i++)
        #pragma unroll
        for (int j=0;j<2;j++) wmma::fill_fragment(c[i][j], 0.f);

    for (int k0 = 0; k0 < K; k0 += 16) {
        #pragma unroll
        for (int t=0;t<2;t++) {                       // A tile 64x16
            int idx = tid + t*128;                    // 0..255
            int row = idx >> 2;
            int kq  = idx & 3;
            float4 v = *(const float4*)(A + (size_t)(bm+row)*lda + k0 + kq*4);
            *(float4*)&As[row*20 + kq*4] = v;
        }
        #pragma unroll
        for (int t=0;t<2;t++) {                       // B tile 16x64
            int idx = tid + t*128;
            int kr = idx >> 4;
            int nq = idx & 15;
            float4 v = *(const float4*)(W + (size_t)(k0+kr)*ldb + bn + nq*4);
            *(float4*)&Bs[kr*68 + nq*4] = v;
        }
        __syncthreads();
        #pragma unroll
        for (int ks=0; ks<2; ks++) {
            wmma::fragment<wmma::matrix_a, 16,16,8, wmma::precision::tf32, wmma::row_major> a[2];
            wmma::fragment<wmma::matrix_b, 16,16,8, wmma::precision::tf32, wmma::row_major> b[2];
            #pragma unroll
            for (int i=0;i<2;i++) {
                wmma::load_matrix_sync(a[i], &As[(wm*32 + i*16)*20 + ks*8], 20);
                #pragma unroll
                for (int e=0;e<a[i].num_elements;e++) a[i].x[e] = wmma::__float_to_tf32(a[i].x[e]);
            }
            #pragma unroll
            for (int j=0;j<2;j++) {
                wmma::load_matrix_sync(b[j], &Bs[(ks*8)*68 + wn*32 + j*16], 68);
                #pragma unroll
                for (int e=0;e<b[j].num_elements;e++) b[j].x[e] = wmma::__float_to_tf32(b[j].x[e]);
            }
            #pragma unroll
            for (int i=0;i<2;i++)
                #pragma unroll
                for (int j=0;j<2;j++)
                    wmma::mma_sync(c[i][j], a[i], b[j], c[i][j]);
        }
        __syncthreads();
    }

    float* Cs = smem;                    // [64][68]
    #pragma unroll
    for (int i=0;i<2;i++)
        #pragma unroll
        for (int j=0;j<2;j++)
            wmma::store_matrix_sync(&Cs[(wm*32+i*16)*68 + wn*32 + j*16], c[i][j], 68, wmma::mem_row_major);
    __syncthreads();
    #pragma unroll
    for (int t=0;t<8;t++) {
        int idx = tid + t*128;            // 1024 float4 slots
        int row = idx >> 4;
        int nq  = idx & 15;
        float4 v  = *(float4*)&Cs[row*68 + nq*4];
        float4 bv = *(const float4*)(bias + bn + nq*4);
        v.x += bv.x; v.y += bv.y; v.z += bv.z; v.w += bv.w;
        *(float4*)(C + (size_t)(bm+row)*ldc + bn + nq*4) = v;
    }
}

// ---------------- SGEMM (fp32 FFMA): C = A@W + bias (+res) (+relu) --------
template<int BM,int BN,int BK,int TM,int TN>
__global__ void sgemm_kernel(int M, int N, int K,
                             const float* __restrict__ A, int lda,
                             const float* __restrict__ W, int ldb,
                             const float* __restrict__ bias,
                             const float* res, int ldres, int relu,
                             float* C, int ldc)
{
    constexpr int THREADS = (BM/TM)*(BN/TN);
    __shared__ float As[BK][BM];
    __shared__ float Bs[BK][BN];
    const int tid = threadIdx.x;
    const int bm = blockIdx.y * BM;
    const int bn = blockIdx.x * BN;
    const int tc = tid % (BN/TN);
    const int tr = tid / (BN/TN);

    float acc[TM][TN];
    #pragma unroll
    for (int i=0;i<TM;i++)
        #pragma unroll
        for (int j=0;j<TN;j++) acc[i][j] = 0.f;

    constexpr int A_F4 = (BM*BK)/(4*THREADS);
    constexpr int B_F4 = (BK*BN)/(4*THREADS);

    for (int k0 = 0; k0 < K; k0 += BK) {
        #pragma unroll
        for (int t = 0; t < A_F4; t++) {
            int idx = tid + t*THREADS;
            int row = idx / (BK/4);
            int kq  = idx % (BK/4);
            float4 v = *(const float4*)(A + (size_t)(bm+row)*lda + k0 + kq*4);
            As[kq*4+0][row] = v.x;
            As[kq*4+1][row] = v.y;
            As[kq*4+2][row] = v.z;
            As[kq*4+3][row] = v.w;
        }
        #pragma unroll
        for (int t = 0; t < B_F4; t++) {
            int idx = tid + t*THREADS;
            int kr = idx / (BN/4);
            int nq = idx % (BN/4);
            float4 v = *(const float4*)(W + (size_t)(k0+kr)*ldb + bn + nq*4);
            *(float4*)&Bs[kr][nq*4] = v;
        }
        __syncthreads();
        #pragma unroll
        for (int kk = 0; kk < BK; kk++) {
            float ra[TM], rb[TN];
            #pragma unroll
            for (int i=0;i<TM;i++) ra[i] = As[kk][tr*TM+i];
            #pragma unroll
            for (int j=0;j<TN;j++) rb[j] = Bs[kk][tc*TN+j];
            #pragma unroll
            for (int i=0;i<TM;i++)
                #pragma unroll
                for (int j=0;j<TN;j++) acc[i][j] += ra[i]*rb[j];
        }
        __syncthreads();
    }

    #pragma unroll
    for (int i=0;i<TM;i++) {
        int row = bm + tr*TM + i;
        #pragma unroll
        for (int j=0;j<TN;j++) {
            int col = bn + tc*TN + j;
            float v = acc[i][j];
            if (bias) v += bias[col];
            if (res)  v += res[(size_t)row*ldres + col];
            if (relu) v = fmaxf(v, 0.f);
            C[(size_t)row*ldc + col] = v;
        }
    }
}

static void launch_gemm(const float* A, int lda, const float* W, int ldb,
                        const float* bias, const float* res, int ldres, int relu,
                        float* C, int ldc, int M, int N, int K)
{
    if (M >= 8192 && (M % 128) == 0 && (N % 128) == 0) {
        dim3 grid(N/128, M/128);
        sgemm_kernel<128,128,16,8,8><<<grid,256>>>(M,N,K,A,lda,W,ldb,bias,res,ldres,relu,C,ldc);
    } else {
        dim3 grid(N/64, M/64);
        sgemm_kernel<64,64,16,4,4><<<grid,256>>>(M,N,K,A,lda,W,ldb,bias,res,ldres,relu,C,ldc);
    }
}

static void launch_gemm_tf32(const float* A, const float* W, const float* bias,
                             float* C, int M, int N, int K)
{
    dim3 grid(N/64, M/64);
    tf32_gemm_kernel<<<grid,128>>>(M,N,K,A,K,W,N,bias,C,N);
}

// ---------------- LayerNorm (row = 512 elems) --------------------------
__global__ void ln_kernel(const float* __restrict__ X,
                          const float* __restrict__ g,
                          const float* __restrict__ b,
                          float* __restrict__ Y)
{
    const int row = blockIdx.x;
    const int tid = threadIdx.x;
    const float* x = X + (size_t)row * D;
    float v0 = x[tid], v1 = x[tid+256];
    __shared__ float red[16];

    float s = v0 + v1;
    #pragma unroll
    for (int o=16;o>0;o>>=1) s += __shfl_xor_sync(0xffffffffu, s, o);
    if ((tid & 31) == 0) red[tid>>5] = s;
    __syncthreads();
    if (tid < 32) {
        float t = (tid < 8) ? red[tid] : 0.f;
        #pragma unroll
        for (int o=4;o>0;o>>=1) t += __shfl_xor_sync(0xffffffffu, t, o);
        if (tid == 0) red[8] = t;
    }
    __syncthreads();
    const float mean = red[8] * (1.f/512.f);
    const float d0 = v0 - mean, d1 = v1 - mean;
    s = d0*d0 + d1*d1;
    #pragma unroll
    for (int o=16;o>0;o>>=1) s += __shfl_xor_sync(0xffffffffu, s, o);
    if ((tid & 31) == 0) red[tid>>5] = s;
    __syncthreads();
    if (tid < 32) {
        float t = (tid < 8) ? red[tid] : 0.f;
        #pragma unroll
        for (int o=4;o>0;o>>=1) t += __shfl_xor_sync(0xffffffffu, t, o);
        if (tid == 0) red[9] = t;
    }
    __syncthreads();
    const float stdv = sqrtf(red[9] * (1.f/512.f));
    const float inv = 1.f / (stdv + 1e-6f);
    Y[(size_t)row*D + tid      ] = g[tid]     * d0 * inv + b[tid];
    Y[(size_t)row*D + tid + 256] = g[tid+256] * d1 * inv + b[tid+256];
}

// ---------------- generic strided attention ----------------------------
__global__ void attn_kernel(const float* __restrict__ Q,
                            const float* __restrict__ K,
                            const float* __restrict__ V,
                            float* __restrict__ O,
                            const int* __restrict__ mask,
                            int maskMode, int maskDiv,
                            int Lq, int Lk,
                            int qDiv, int kOuter, int kDiv, int kStride,
                            float scale)
{
    extern __shared__ float sm[];
    float* Ks = sm;
    float* Vs = Ks + Lk*65;
    float* qs = Vs + Lk*65;
    float* ps = qs + 4*64;

    const int i = blockIdx.x;
    const int h = blockIdx.y;
    const int tid = threadIdx.x;
    const int lane = tid & 31;
    const int w = tid >> 5;

    const size_t kBase = (size_t)(i/kDiv)*kOuter + (size_t)(i%kDiv);

    for (int idx = tid; idx < Lk*64; idx += 128) {
        int tk = idx >> 6, d = idx & 63;
        size_t grow = (kBase + (size_t)tk*kStride)*D + h*DK + d;
        Ks[tk*65+d] = K[grow];
        Vs[tk*65+d] = V[grow];
    }
    __syncthreads();

    const int qb = (i/qDiv) * Lq;
    const int nj = (Lk + 31) >> 5;

    for (int tq = w; tq < Lq; tq += 4) {
        size_t qoff = (size_t)(qb + tq)*D + h*DK;
        qs[w*64 + lane]      = Q[qoff + lane];
        qs[w*64 + lane + 32] = Q[qoff + lane + 32];
        __syncwarp();

        float sc[4];
        #pragma unroll
        for (int j=0;j<4;j++) sc[j] = -INFINITY;

        for (int j=0;j<nj;j++) {
            int k = lane + (j<<5);
            if (k < Lk) {
                float dot = 0.f;
                const float* kr = Ks + k*65;
                const float* qq = qs + w*64;
                #pragma unroll
                for (int d=0; d<64; d++) dot += qq[d]*kr[d];
                dot *= scale;
                if (maskMode == 1) {
                    if (mask[(size_t)(i/maskDiv)*Lk + k] == 0) dot = -1e9f;
                } else if (maskMode == 2) {
                    if (mask[((size_t)i*Lq + tq)*Lk + k] == 0) dot = -1e9f;
                }
                sc[j] = dot;
            }
        }
        float mx = -INFINITY;
        for (int j=0;j<nj;j++) mx = fmaxf(mx, sc[j]);
        #pragma unroll
        for (int o=16;o>0;o>>=1) mx = fmaxf(mx, __shfl_xor_sync(0xffffffffu, mx, o));

        float e[4]; float sum = 0.f;
        for (int j=0;j<nj;j++) {
            e[j] = (sc[j] == -INFINITY) ? 0.f : __expf(sc[j] - mx);
            sum += e[j];
        }
        #pragma unroll
        for (int o=16;o>0;o>>=1) sum += __shfl_xor_sync(0xffffffffu, sum, o);
        const float inv = 1.f / sum;
        for (int j=0;j<nj;j++) {
            int k = lane + (j<<5);
            if (k < Lk) ps[w*Lk + k] = e[j] * inv;
        }
        __syncwarp();

        float o0 = 0.f, o1 = 0.f;
        for (int k=0;k<Lk;k++) {
            float p = ps[w*Lk + k];
            o0 += p * Vs[k*65 + lane];
            o1 += p * Vs[k*65 + lane + 32];
        }
        size_t orow = ((size_t)i*Lq + tq)*D + h*DK;
        O[orow + lane]      = o0;
        O[orow + lane + 32] = o1;
        __syncwarp();
    }
}

static void launch_attn(const float* Q, const float* K, const float* V, float* O,
                        const int* mask, int maskMode, int maskDiv,
                        int nb, int Lq, int Lk,
                        int qDiv, int kOuter, int kDiv, int kStride)
{
    dim3 grid(nb, NH);
    size_t smem = (size_t)(2*Lk*65 + 4*64 + 4*Lk) * sizeof(float);
    attn_kernel<<<grid, 128, smem>>>(Q, K, V, O, mask, maskMode, maskDiv,
                                     Lq, Lk, qDiv, kOuter, kDiv, kStride, 0.125f);
}

// ---------------- fold attention (Lq=1 per unit; K/V folded) ------------
__global__ void fold_attn_kernel(const float* __restrict__ O,
                                 const float* __restrict__ Qo,
                                 const float* __restrict__ sb,
                                 const int* __restrict__ mask, int maskApply,
                                 float* __restrict__ ctx, int Lk)
{
    extern __shared__ float sm[];
    float* Os = sm;               // Lk*512
    float* sc = Os + Lk*512;      // 8*64
    float* pp = sc + 512;         // 8*64

    const int u = blockIdx.x;
    const int tid = threadIdx.x;
    const int h = tid >> 5;
    const int lane = tid & 31;
    const size_t base = (size_t)(u >> 6) * Lk * 64 + (u & 63);

    for (int idx = tid; idx < Lk*512; idx += 256) {
        int s = idx >> 9, d = idx & 511;
        Os[idx] = O[(base + (size_t)s*64)*D + d];
    }
    __syncthreads();

    float qreg[16];
    #pragma unroll
    for (int i=0;i<16;i++) qreg[i] = Qo[(size_t)u*(NH*D) + h*D + i*32 + lane];

    const float sbase = sb[u*NH + h];

    for (int s = 0; s < Lk; s++) {
        float dot = 0.f;
        const float* row = Os + s*512;
        #pragma unroll
        for (int i=0;i<16;i++) dot += qreg[i] * row[i*32 + lane];
        #pragma unroll
        for (int o=16;o>0;o>>=1) dot += __shfl_xor_sync(0xffffffffu, dot, o);
        float score = (sbase + dot) * 0.125f;
        if (maskApply && mask[(u>>6)*Lk + s] == 0) score = -1e9f;
        if (lane == 0) sc[h*64 + s] = score;
    }
    __syncwarp();

    float v0 = (lane      < Lk) ? sc[h*64 + lane]      : -INFINITY;
    float v1 = (lane + 32 < Lk) ? sc[h*64 + lane + 32] : -INFINITY;
    float mx = fmaxf(v0, v1);
    #pragma unroll
    for (int o=16;o>0;o>>=1) mx = fmaxf(mx, __shfl_xor_sync(0xffffffffu, mx, o));
    float e0 = (lane      < Lk) ? __expf(v0 - mx) : 0.f;
    float e1 = (lane + 32 < Lk) ? __expf(v1 - mx) : 0.f;
    float sum = e0 + e1;
    #pragma unroll
    for (int o=16;o>0;o>>=1) sum += __shfl_xor_sync(0xffffffffu, sum, o);
    const float inv = 1.f / sum;
    if (lane      < Lk) pp[h*64 + lane]      = e0 * inv;
    if (lane + 32 < Lk) pp[h*64 + lane + 32] = e1 * inv;
    __syncwarp();

    #pragma unroll
    for (int i=0;i<16;i++) {
        float acc = 0.f;
        for (int s=0;s<Lk;s++)
            acc += pp[h*64 + s] * Os[s*512 + i*32 + lane];
        ctx[(size_t)u*(NH*D) + h*D + i*32 + lane] = acc;
    }
}

// ---------------- small helpers ----------------
__global__ void transpose512(const float* __restrict__ in, float* __restrict__ out)
{
    __shared__ float t[32][33];
    int bx = blockIdx.x*32, by = blockIdx.y*32;
    for (int j = threadIdx.y; j < 32; j += 8)
        t[j][threadIdx.x] = in[(size_t)(by+j)*D + bx + threadIdx.x];
    __syncthreads();
    for (int j = threadIdx.y; j < 32; j += 8)
        out[(size_t)(bx+j)*D + by + threadIdx.x] = t[threadIdx.x][j];
}

__global__ void addrow_kernel(const float* __restrict__ a, const float* __restrict__ bvec,
                              float* __restrict__ c)
{
    int u = blockIdx.x, d = threadIdx.x;
    c[(size_t)u*D + d] = a[(size_t)u*D + d] + bvec[d];
}

__global__ void sbase_kernel(const float* __restrict__ Qp, const float* __restrict__ mmk,
                             float* __restrict__ sb)
{
    int u = blockIdx.x;
    int h = threadIdx.x >> 5, lane = threadIdx.x & 31;
    const float* q = Qp  + (size_t)u*D + h*64;
    const float* m = mmk + (size_t)u*D + h*64;
    float s = q[lane]*m[lane] + q[lane+32]*m[lane+32];
    #pragma unroll
    for (int o=16;o>0;o>>=1) s += __shfl_xor_sync(0xffffffffu, s, o);
    if (lane == 0) sb[u*NH + h] = s;
}

__global__ void add_kernel(const float* __restrict__ a, const float* __restrict__ b,
                           float* __restrict__ c, int n)
{
    int i = blockIdx.x*256 + threadIdx.x;
    if (i < n) c[i] = a[i] + b[i];
}

// ---------------- driver ----------------
extern "C" void kernel_launch(void* const* d_in, const int* in_sizes, int n_in,
                              void* d_out, int out_size)
{
    const float* x        = (const float*)d_in[0];
    const float* vft      = (const float*)d_in[1];
    const float* enc_his  = (const float*)d_in[2];
    const float* enc_cap  = (const float*)d_in[3];
    const float* enc_qry  = (const float*)d_in[4];
    const int*   trg_mask = (const int*)  d_in[5];
    const int*   his_mask = (const int*)  d_in[6];
    const int*   cap_mask = (const int*)  d_in[7];
    const int*   qry_mask = (const int*)  d_in[8];
    const int*   tmp_mask = (const int*)  d_in[9];
    const float* attn_w   = (const float*)d_in[10];
    const float* attn_b   = (const float*)d_in[11];
    const float* ff_w1    = (const float*)d_in[12];
    const float* ff_b1    = (const float*)d_in[13];
    const float* ff_w2    = (const float*)d_in[14];
    const float* ff_b2    = (const float*)d_in[15];
    const float* ln_g     = (const float*)d_in[16];
    const float* ln_b     = (const float*)d_in[17];
    float* outp = (float*)d_out;

    float *big0,*big1,*big2,*big3,*lnb,*qb,*ob,*cur,*ts,*st,*kb,*vb,*mid;
    float *mmb,*mmk,*mmv,*sb,*qo,*ctx,*w1,*w1t,*w2;
    cudaGetSymbolAddress((void**)&big0, g_big0);
    cudaGetSymbolAddress((void**)&big1, g_big1);
    cudaGetSymbolAddress((void**)&big2, g_big2);
    cudaGetSymbolAddress((void**)&big3, g_big3);
    cudaGetSymbolAddress((void**)&lnb,  g_ln);
    cudaGetSymbolAddress((void**)&qb,   g_q);
    cudaGetSymbolAddress((void**)&ob,   g_o);
    cudaGetSymbolAddress((void**)&cur,  g_cur);
    cudaGetSymbolAddress((void**)&ts,   g_ts);
    cudaGetSymbolAddress((void**)&st,   g_st);
    cudaGetSymbolAddress((void**)&kb,   g_k);
    cudaGetSymbolAddress((void**)&vb,   g_v);
    cudaGetSymbolAddress((void**)&mid,  g_mid);
    cudaGetSymbolAddress((void**)&mmb,  g_mmb);
    cudaGetSymbolAddress((void**)&mmk,  g_mmk);
    cudaGetSymbolAddress((void**)&mmv,  g_mmv);
    cudaGetSymbolAddress((void**)&sb,   g_sb);
    cudaGetSymbolAddress((void**)&qo,   g_qo);
    cudaGetSymbolAddress((void**)&ctx,  g_ctx);
    cudaGetSymbolAddress((void**)&w1,   g_w1);
    cudaGetSymbolAddress((void**)&w1t,  g_w1t);
    cudaGetSymbolAddress((void**)&w2,   g_w2);

    cudaFuncSetAttribute(attn_kernel, cudaFuncAttributeMaxDynamicSharedMemorySize, 73728);
    cudaFuncSetAttribute(fold_attn_kernel, cudaFuncAttributeMaxDynamicSharedMemorySize, 64*512*4 + 4096);

    #define WATT(l,j) (attn_w + ((size_t)(l)*4+(j))*D*D)
    #define BATT(l,j) (attn_b + ((size_t)(l)*4+(j))*D)

    // ===== MHA0: self-attn, causal mask =====
    ln_kernel<<<NT,256>>>(x, ln_g + 0*D, ln_b + 0*D, lnb);
    launch_gemm(lnb,D, WATT(0,0),D, BATT(0,0), nullptr,0,0, qb,D, NT, D, D);
    launch_gemm(lnb,D, WATT(0,1),D, BATT(0,1), nullptr,0,0, kb,D, NT, D, D);
    launch_gemm(lnb,D, WATT(0,2),D, BATT(0,2), nullptr,0,0, vb,D, NT, D, D);
    launch_attn(qb, kb, vb, ob, trg_mask, 2, 1, BSZ, TTRG, TTRG, 1, TTRG, 1, 1);
    launch_gemm(ob,D, WATT(0,3),D, BATT(0,3), x,D,0, cur,D, NT, D, D);

    // ===== MHA1: cross-attn encoded_his (Lk=128) =====
    ln_kernel<<<NT,256>>>(cur, ln_g + 1*D, ln_b + 1*D, lnb);
    launch_gemm(lnb,D,     WATT(1,0),D, BATT(1,0), nullptr,0,0, qb,D, NT,   D, D);
    launch_gemm(enc_his,D, WATT(1,1),D, BATT(1,1), nullptr,0,0, kb,D, 2048, D, D);
    launch_gemm(enc_his,D, WATT(1,2),D, BATT(1,2), nullptr,0,0, vb,D, 2048, D, D);
    launch_attn(qb, kb, vb, ob, his_mask, 1, 1, BSZ, TTRG, 128, 1, 128, 1, 1);
    launch_gemm(ob,D, WATT(1,3),D, BATT(1,3), cur,D,0, cur,D, NT, D, D);

    // ===== MHA2: cross-attn encoded_cap (Lk=64) =====
    ln_kernel<<<NT,256>>>(cur, ln_g + 2*D, ln_b + 2*D, lnb);
    launch_gemm(lnb,D,     WATT(2,0),D, BATT(2,0), nullptr,0,0, qb,D, NT,   D, D);
    launch_gemm(enc_cap,D, WATT(2,1),D, BATT(2,1), nullptr,0,0, kb,D, 1024, D, D);
    launch_gemm(enc_cap,D, WATT(2,2),D, BATT(2,2), nullptr,0,0, vb,D, 1024, D, D);
    launch_attn(qb, kb, vb, ob, cap_mask, 1, 1, BSZ, TTRG, 64, 1, 64, 1, 1);
    launch_gemm(ob,D, WATT(2,3),D, BATT(2,3), cur,D,0, cur,D, NT, D, D);

    // ===== MHA3: cross-attn encoded_query (Lk=32) -> mm (cur) =====
    ln_kernel<<<NT,256>>>(cur, ln_g + 3*D, ln_b + 3*D, lnb);
    launch_gemm(lnb,D,     WATT(3,0),D, BATT(3,0), nullptr,0,0, qb,D, NT,  D, D);
    launch_gemm(enc_qry,D, WATT(3,1),D, BATT(3,1), nullptr,0,0, kb,D, 512, D, D);
    launch_gemm(enc_qry,D, WATT(3,2),D, BATT(3,2), nullptr,0,0, vb,D, 512, D, D);
    launch_attn(qb, kb, vb, ob, qry_mask, 1, 1, BSZ, TTRG, 32, 1, 32, 1, 1);
    launch_gemm(ob,D, WATT(3,3),D, BATT(3,3), cur,D,0, cur,D, NT, D, D);
    // cur == mm from here on

    // ===== temporal2spatial: MHA4 over T per spatial location =====
    ln_kernel<<<NT,256>>>(cur, ln_g + 4*D, ln_b + 4*D, lnb);
    launch_gemm(lnb,D, WATT(4,0),D, BATT(4,0), nullptr,0,0, qb,D, NT, D, D);
    launch_gemm_tf32(vft, WATT(4,1), BATT(4,1), big0, NV, D, D);   // K4 (tensor core)
    launch_gemm_tf32(vft, WATT(4,2), BATT(4,2), big1, NV, D, D);   // V4 (tensor core)
    launch_attn(qb, big0, big1, big2, tmp_mask, 1, SSP,
                BSZ*SSP, TTRG, TT, SSP, TT*SSP, SSP, SSP);                       // O4

    // ===== MHA5 (folded): 1 query over S; K/V = mm_bcast + O4@Wo4 =====
    {
        const float* Wo = WATT(4,3); const float* bo = BATT(4,3);
        const float* Wq = WATT(5,0), *Wk = WATT(5,1), *Wv = WATT(5,2), *Wo5 = WATT(5,3);
        addrow_kernel<<<NT,512>>>(cur, bo, mmb);
        launch_gemm(mmb,D, Wk,D, BATT(5,1), nullptr,0,0, mmk,D, NT, D, D);
        launch_gemm(mmb,D, Wv,D, BATT(5,2), nullptr,0,0, mmv,D, NT, D, D);
        ln_kernel<<<NT,256>>>(cur, ln_g + 5*D, ln_b + 5*D, lnb);
        launch_gemm(lnb,D, Wq,D, BATT(5,0), nullptr,0,0, qb,D, NT, D, D);        // Qp
        launch_gemm(Wo,D, Wk,D, nullptr, nullptr,0,0, w1,D, D, D, D);            // WoWk
        transpose512<<<dim3(16,16),dim3(32,8)>>>(w1, w1t);
        launch_gemm(Wo,D, Wv,D, nullptr, nullptr,0,0, w2,D, D, D, D);            // WoWv
        for (int h=0; h<NH; h++)                                                  // Qo_h
            launch_gemm(qb + h*64, D, w1t + (size_t)h*64*D, D, nullptr, nullptr,0,0,
                        qo + h*D, NH*D, NT, D, 64);
        sbase_kernel<<<NT,256>>>(qb, mmk, sb);
        fold_attn_kernel<<<NT,256, SSP*512*4 + 4096>>>(big2, qo, sb, nullptr, 0, ctx, SSP);
        for (int h=0; h<NH; h++)                                                  // attn_out slice
            launch_gemm(ctx + h*D, NH*D, w2 + h*64, D, nullptr, mmv + h*64, D, 0,
                        ob + h*64, D, NT, 64, D);
        launch_gemm(ob,D, Wo5,D, BATT(5,3), cur,D,0, ts,D, NT, D, D);
    }

    // ===== FFN0 on ts =====
    ln_kernel<<<NT,256>>>(ts, ln_g + 6*D, ln_b + 6*D, lnb);
    launch_gemm(lnb,D, ff_w1 + 0*(size_t)D*DFF,DFF, ff_b1 + 0*DFF, nullptr,0,1, mid,DFF, NT, DFF, D);
    launch_gemm(mid,DFF, ff_w2 + 0*(size_t)DFF*D,D, ff_b2 + 0*D, ts,D,0, ts,D, NT, D, DFF);

    // ===== spatial2temporal: MHA6 over S per frame =====
    ln_kernel<<<NT,256>>>(cur, ln_g + 7*D, ln_b + 7*D, lnb);
    launch_gemm(lnb,D, WATT(6,0),D, BATT(6,0), nullptr,0,0, qb,D, NT, D, D);
    launch_gemm_tf32(vft, WATT(6,1), BATT(6,1), big0, NV, D, D);   // K6 (tensor core)
    launch_gemm_tf32(vft, WATT(6,2), BATT(6,2), big1, NV, D, D);   // V6 (tensor core)
    launch_attn(qb, big0, big1, big3, nullptr, 0, 1,
                BSZ*TT, TTRG, SSP, TT, SSP, 1, 1);                               // O6

    // ===== MHA7 (folded): 1 query over T; K/V = mm_bcast + O6@Wo6; temporal mask =====
    {
        const float* Wo = WATT(6,3); const float* bo = BATT(6,3);
        const float* Wq = WATT(7,0), *Wk = WATT(7,1), *Wv = WATT(7,2), *Wo7 = WATT(7,3);
        addrow_kernel<<<NT,512>>>(cur, bo, mmb);
        launch_gemm(mmb,D, Wk,D, BATT(7,1), nullptr,0,0, mmk,D, NT, D, D);
        launch_gemm(mmb,D, Wv,D, BATT(7,2), nullptr,0,0, mmv,D, NT, D, D);
        ln_kernel<<<NT,256>>>(cur, ln_g + 8*D, ln_b + 8*D, lnb);
        launch_gemm(lnb,D, Wq,D, BATT(7,0), nullptr,0,0, qb,D, NT, D, D);
        launch_gemm(Wo,D, Wk,D, nullptr, nullptr,0,0, w1,D, D, D, D);
        transpose512<<<dim3(16,16),dim3(32,8)>>>(w1, w1t);
        launch_gemm(Wo,D, Wv,D, nullptr, nullptr,0,0, w2,D, D, D, D);
        for (int h=0; h<NH; h++)
            launch_gemm(qb + h*64, D, w1t + (size_t)h*64*D, D, nullptr, nullptr,0,0,
                        qo + h*D, NH*D, NT, D, 64);
        sbase_kernel<<<NT,256>>>(qb, mmk, sb);
        fold_attn_kernel<<<NT,256, TT*512*4 + 4096>>>(big3, qo, sb, tmp_mask, 1, ctx, TT);
        for (int h=0; h<NH; h++)
            launch_gemm(ctx + h*D, NH*D, w2 + h*64, D, nullptr, mmv + h*64, D, 0,
                        ob + h*64, D, NT, 64, D);
        launch_gemm(ob,D, Wo7,D, BATT(7,3), cur,D,0, st,D, NT, D, D);
    }

    // ===== FFN1 on st =====
    ln_kernel<<<NT,256>>>(st, ln_g + 9*D, ln_b + 9*D, lnb);
    launch_gemm(lnb,D, ff_w1 + 1*(size_t)D*DFF,DFF, ff_b1 + 1*DFF, nullptr,0,1, mid,DFF, NT, DFF, D);
    launch_gemm(mid,DFF, ff_w2 + 1*(size_t)DFF*D,D, ff_b2 + 1*D, st,D,0, st,D, NT, D, DFF);

    // ===== out = ts + st; FFN2 =====
    add_kernel<<<(NT*D+255)/256,256>>>(ts, st, qb, NT*D);
    ln_kernel<<<NT,256>>>(qb, ln_g + 10*D, ln_b + 10*D, lnb);
    launch_gemm(lnb,D, ff_w1 + 2*(size_t)D*DFF,DFF, ff_b1 + 2*DFF, nullptr,0,1, mid,DFF, NT, DFF, D);
    launch_gemm(mid,DFF, ff_w2 + 2*(size_t)DFF*D,D, ff_b2 + 2*D, qb,D,0, outp,D, NT, D, DFF);
}

// round 6
// speedup vs baseline: 1.8328x; 1.0971x over previous
#include <cuda_runtime.h>
#include <math.h>
#include <stdint.h>
#include <mma.h>
using namespace nvcuda;

// ---------------- constants ----------------
#define D     512
#define NH    8
#define DK    64
#define BSZ   16
#define TTRG  64
#define TT    64
#define SSP   49
#define DFF   2048
#define NT    1024      /* B*Ttrg */
#define NV    50176     /* B*T*S  */
#define NBIG  65536     /* B*T*Ttrg -- O6 row count; big3 MUST be this size */

// ---------------- scratch ----------------
__device__ float g_big0[(size_t)NV * D];
__device__ float g_big1[(size_t)NV * D];
__device__ float g_big2[(size_t)NV * D];     // O4: BSZ*SSP*TTRG = 50176 rows
__device__ float g_big3[(size_t)NBIG * D];   // O6: BSZ*TT*TTRG = 65536 rows
__device__ float g_ln [(size_t)NT * D];
__device__ float g_q  [(size_t)NT * D];
__device__ float g_o  [(size_t)NT * D];
__device__ float g_cur[(size_t)NT * D];
__device__ float g_ts [(size_t)NT * D];
__device__ float g_st [(size_t)NT * D];
__device__ float g_k  [(size_t)2048 * D];
__device__ float g_v  [(size_t)2048 * D];
__device__ float g_mid[(size_t)NT * DFF];
__device__ float g_mmb[(size_t)NT * D];
__device__ float g_mmk[(size_t)NT * D];
__device__ float g_mmv[(size_t)NT * D];
__device__ float g_sb [(size_t)NT * NH];
__device__ float g_qo [(size_t)NT * NH * D];
__device__ float g_ctx[(size_t)NT * NH * D];
__device__ float g_w1 [(size_t)D * D];
__device__ float g_w1t[(size_t)D * D];
__device__ float g_w2 [(size_t)D * D];

// ================= tf32 GEMM, 128x128x32 tile (big M) =====================
__global__ void tf32_gemm_big(int M, int N, int K,
                              const float* __restrict__ A, int lda,
                              const float* __restrict__ W, int ldb,
                              const float* __restrict__ bias,
                              const float* res, int ldres, int relu,
                              float* __restrict__ C, int ldc)
{
    extern __shared__ float sm[];
    float* As = sm;              // [128][36]
    float* Bs = sm + 128*36;     // [32][132]
    const int tid = threadIdx.x;
    const int wid = tid >> 5;
    const int wm = wid >> 1;     // 0..3
    const int wn = wid & 1;      // 0..1
    const int bm = blockIdx.y * 128;
    const int bn = blockIdx.x * 128;

    wmma::fragment<wmma::accumulator, 16,16,8, float> c[2][4];
    #pragma unroll
    for (int i=0;i<2;i++)
        #pragma unroll
        for (int j=0;j<4;j++) wmma::fill_fragment(c[i][j], 0.f);

    for (int k0 = 0; k0 < K; k0 += 32) {
        #pragma unroll
        for (int t=0;t<4;t++) {                      // A: 128x32
            int idx = tid + t*256;
            int row = idx >> 3, q = idx & 7;
            float4 v = *(const float4*)(A + (size_t)(bm+row)*lda + k0 + q*4);
            *(float4*)&As[row*36 + q*4] = v;
        }
        #pragma unroll
        for (int t=0;t<4;t++) {                      // B: 32x128
            int idx = tid + t*256;
            int row = idx >> 5, q = idx & 31;
            float4 v = *(const float4*)(W + (size_t)(k0+row)*ldb + bn + q*4);
            *(float4*)&Bs[row*132 + q*4] = v;
        }
        __syncthreads();
        #pragma unroll
        for (int ks=0; ks<4; ks++) {
            wmma::fragment<wmma::matrix_a, 16,16,8, wmma::precision::tf32, wmma::row_major> a[2];
            wmma::fragment<wmma::matrix_b, 16,16,8, wmma::precision::tf32, wmma::row_major> b[4];
            #pragma unroll
            for (int i=0;i<2;i++) {
                wmma::load_matrix_sync(a[i], &As[(wm*32 + i*16)*36 + ks*8], 36);
                #pragma unroll
                for (int e=0;e<a[i].num_elements;e++) a[i].x[e] = wmma::__float_to_tf32(a[i].x[e]);
            }
            #pragma unroll
            for (int j=0;j<4;j++) {
                wmma::load_matrix_sync(b[j], &Bs[(ks*8)*132 + wn*64 + j*16], 132);
                #pragma unroll
                for (int e=0;e<b[j].num_elements;e++) b[j].x[e] = wmma::__float_to_tf32(b[j].x[e]);
            }
            #pragma unroll
            for (int i=0;i<2;i++)
                #pragma unroll
                for (int j=0;j<4;j++)
                    wmma::mma_sync(c[i][j], a[i], b[j], c[i][j]);
        }
        __syncthreads();
    }

    float* Cs = sm;              // [128][132]
    #pragma unroll
    for (int i=0;i<2;i++)
        #pragma unroll
        for (int j=0;j<4;j++)
            wmma::store_matrix_sync(&Cs[(wm*32+i*16)*132 + wn*64 + j*16], c[i][j], 132, wmma::mem_row_major);
    __syncthreads();
    #pragma unroll
    for (int t=0;t<16;t++) {
        int idx = tid + t*256;
        int row = idx >> 5, q = idx & 31;
        float4 v = *(float4*)&Cs[row*132 + q*4];
        if (bias) {
            float4 bv = *(const float4*)(bias + bn + q*4);
            v.x += bv.x; v.y += bv.y; v.z += bv.z; v.w += bv.w;
        }
        if (res) {
            float4 rv = *(const float4*)(res + (size_t)(bm+row)*ldres + bn + q*4);
            v.x += rv.x; v.y += rv.y; v.z += rv.z; v.w += rv.w;
        }
        if (relu) {
            v.x = fmaxf(v.x,0.f); v.y = fmaxf(v.y,0.f);
            v.z = fmaxf(v.z,0.f); v.w = fmaxf(v.w,0.f);
        }
        *(float4*)(C + (size_t)(bm+row)*ldc + bn + q*4) = v;
    }
}

// ================= tf32 GEMM, 64x64x32 tile (small M) =====================
__global__ void tf32_gemm_small(int M, int N, int K,
                                const float* __restrict__ A, int lda,
                                const float* __restrict__ W, int ldb,
                                const float* __restrict__ bias,
                                const float* res, int ldres, int relu,
                                float* __restrict__ C, int ldc)
{
    __shared__ float sm[4480];
    float* As = sm;              // [64][36]
    float* Bs = sm + 64*36;      // [32][68]
    const int tid = threadIdx.x;
    const int wid = tid >> 5;
    const int wm = wid >> 1;
    const int wn = wid & 1;
    const int bm = blockIdx.y * 64;
    const int bn = blockIdx.x * 64;

    wmma::fragment<wmma::accumulator, 16,16,8, float> c[2][2];
    #pragma unroll
    for (int i=0;i<2;i++)
        #pragma unroll
        for (int j=0;j<2;j++) wmma::fill_fragment(c[i][j], 0.f);

    for (int k0 = 0; k0 < K; k0 += 32) {
        #pragma unroll
        for (int t=0;t<4;t++) {                      // A: 64x32
            int idx = tid + t*128;
            int row = idx >> 3, q = idx & 7;
            float4 v = *(const float4*)(A + (size_t)(bm+row)*lda + k0 + q*4);
            *(float4*)&As[row*36 + q*4] = v;
        }
        #pragma unroll
        for (int t=0;t<4;t++) {                      // B: 32x64
            int idx = tid + t*128;
            int row = idx >> 4, q = idx & 15;
            float4 v = *(const float4*)(W + (size_t)(k0+row)*ldb + bn + q*4);
            *(float4*)&Bs[row*68 + q*4] = v;
        }
        __syncthreads();
        #pragma unroll
        for (int ks=0; ks<4; ks++) {
            wmma::fragment<wmma::matrix_a, 16,16,8, wmma::precision::tf32, wmma::row_major> a[2];
            wmma::fragment<wmma::matrix_b, 16,16,8, wmma::precision::tf32, wmma::row_major> b[2];
            #pragma unroll
            for (int i=0;i<2;i++) {
                wmma::load_matrix_sync(a[i], &As[(wm*32 + i*16)*36 + ks*8], 36);
                #pragma unroll
                for (int e=0;e<a[i].num_elements;e++) a[i].x[e] = wmma::__float_to_tf32(a[i].x[e]);
            }
            #pragma unroll
            for (int j=0;j<2;j++) {
                wmma::load_matrix_sync(b[j], &Bs[(ks*8)*68 + wn*32 + j*16], 68);
                #pragma unroll
                for (int e=0;e<b[j].num_elements;e++) b[j].x[e] = wmma::__float_to_tf32(b[j].x[e]);
            }
            #pragma unroll
            for (int i=0;i<2;i++)
                #pragma unroll
                for (int j=0;j<2;j++)
                    wmma::mma_sync(c[i][j], a[i], b[j], c[i][j]);
        }
        __syncthreads();
    }

    float* Cs = sm;              // [64][68]
    #pragma unroll
    for (int i=0;i<2;i++)
        #pragma unroll
        for (int j=0;j<2;j++)
            wmma::store_matrix_sync(&Cs[(wm*32+i*16)*68 + wn*32 + j*16], c[i][j], 68, wmma::mem_row_major);
    __syncthreads();
    #pragma unroll
    for (int t=0;t<8;t++) {
        int idx = tid + t*128;
        int row = idx >> 4, q = idx & 15;
        float4 v = *(float4*)&Cs[row*68 + q*4];
        if (bias) {
            float4 bv = *(const float4*)(bias + bn + q*4);
            v.x += bv.x; v.y += bv.y; v.z += bv.z; v.w += bv.w;
        }
        if (res) {
            float4 rv = *(const float4*)(res + (size_t)(bm+row)*ldres + bn + q*4);
            v.x += rv.x; v.y += rv.y; v.z += rv.z; v.w += rv.w;
        }
        if (relu) {
            v.x = fmaxf(v.x,0.f); v.y = fmaxf(v.y,0.f);
            v.z = fmaxf(v.z,0.f); v.w = fmaxf(v.w,0.f);
        }
        *(float4*)(C + (size_t)(bm+row)*ldc + bn + q*4) = v;
    }
}

// ---------------- fallback fp32 SGEMM ----------------
template<int BM,int BN,int BK,int TM,int TN>
__global__ void sgemm_kernel(int M, int N, int K,
                             const float* __restrict__ A, int lda,
                             const float* __restrict__ W, int ldb,
                             const float* __restrict__ bias,
                             const float* res, int ldres, int relu,
                             float* C, int ldc)
{
    constexpr int THREADS = (BM/TM)*(BN/TN);
    __shared__ float As[BK][BM];
    __shared__ float Bs[BK][BN];
    const int tid = threadIdx.x;
    const int bm = blockIdx.y * BM;
    const int bn = blockIdx.x * BN;
    const int tc = tid % (BN/TN);
    const int tr = tid / (BN/TN);

    float acc[TM][TN];
    #pragma unroll
    for (int i=0;i<TM;i++)
        #pragma unroll
        for (int j=0;j<TN;j++) acc[i][j] = 0.f;

    constexpr int A_F4 = (BM*BK)/(4*THREADS);
    constexpr int B_F4 = (BK*BN)/(4*THREADS);

    for (int k0 = 0; k0 < K; k0 += BK) {
        #pragma unroll
        for (int t = 0; t < A_F4; t++) {
            int idx = tid + t*THREADS;
            int row = idx / (BK/4);
            int kq  = idx % (BK/4);
            float4 v = *(const float4*)(A + (size_t)(bm+row)*lda + k0 + kq*4);
            As[kq*4+0][row] = v.x;
            As[kq*4+1][row] = v.y;
            As[kq*4+2][row] = v.z;
            As[kq*4+3][row] = v.w;
        }
        #pragma unroll
        for (int t = 0; t < B_F4; t++) {
            int idx = tid + t*THREADS;
            int kr = idx / (BN/4);
            int nq = idx % (BN/4);
            float4 v = *(const float4*)(W + (size_t)(k0+kr)*ldb + bn + nq*4);
            *(float4*)&Bs[kr][nq*4] = v;
        }
        __syncthreads();
        #pragma unroll
        for (int kk = 0; kk < BK; kk++) {
            float ra[TM], rb[TN];
            #pragma unroll
            for (int i=0;i<TM;i++) ra[i] = As[kk][tr*TM+i];
            #pragma unroll
            for (int j=0;j<TN;j++) rb[j] = Bs[kk][tc*TN+j];
            #pragma unroll
            for (int i=0;i<TM;i++)
                #pragma unroll
                for (int j=0;j<TN;j++) acc[i][j] += ra[i]*rb[j];
        }
        __syncthreads();
    }

    #pragma unroll
    for (int i=0;i<TM;i++) {
        int row = bm + tr*TM + i;
        #pragma unroll
        for (int j=0;j<TN;j++) {
            int col = bn + tc*TN + j;
            float v = acc[i][j];
            if (bias) v += bias[col];
            if (res)  v += res[(size_t)row*ldres + col];
            if (relu) v = fmaxf(v, 0.f);
            C[(size_t)row*ldc + col] = v;
        }
    }
}

static void launch_gemm(const float* A, int lda, const float* W, int ldb,
                        const float* bias, const float* res, int ldres, int relu,
                        float* C, int ldc, int M, int N, int K)
{
    if ((M % 64) == 0 && (N % 64) == 0 && (K % 32) == 0) {
        if (M >= 4096 && (M % 128) == 0 && (N % 128) == 0) {
            dim3 grid(N/128, M/128);
            tf32_gemm_big<<<grid,256,128*132*4>>>(M,N,K,A,lda,W,ldb,bias,res,ldres,relu,C,ldc);
        } else {
            dim3 grid(N/64, M/64);
            tf32_gemm_small<<<grid,128>>>(M,N,K,A,lda,W,ldb,bias,res,ldres,relu,C,ldc);
        }
    } else {
        dim3 grid(N/64, M/64);
        sgemm_kernel<64,64,16,4,4><<<grid,256>>>(M,N,K,A,lda,W,ldb,bias,res,ldres,relu,C,ldc);
    }
}

// ---------------- LayerNorm ----------------
__global__ void ln_kernel(const float* __restrict__ X,
                          const float* __restrict__ g,
                          const float* __restrict__ b,
                          float* __restrict__ Y)
{
    const int row = blockIdx.x;
    const int tid = threadIdx.x;
    const float* x = X + (size_t)row * D;
    float v0 = x[tid], v1 = x[tid+256];
    __shared__ float red[16];

    float s = v0 + v1;
    #pragma unroll
    for (int o=16;o>0;o>>=1) s += __shfl_xor_sync(0xffffffffu, s, o);
    if ((tid & 31) == 0) red[tid>>5] = s;
    __syncthreads();
    if (tid < 32) {
        float t = (tid < 8) ? red[tid] : 0.f;
        #pragma unroll
        for (int o=4;o>0;o>>=1) t += __shfl_xor_sync(0xffffffffu, t, o);
        if (tid == 0) red[8] = t;
    }
    __syncthreads();
    const float mean = red[8] * (1.f/512.f);
    const float d0 = v0 - mean, d1 = v1 - mean;
    s = d0*d0 + d1*d1;
    #pragma unroll
    for (int o=16;o>0;o>>=1) s += __shfl_xor_sync(0xffffffffu, s, o);
    if ((tid & 31) == 0) red[tid>>5] = s;
    __syncthreads();
    if (tid < 32) {
        float t = (tid < 8) ? red[tid] : 0.f;
        #pragma unroll
        for (int o=4;o>0;o>>=1) t += __shfl_xor_sync(0xffffffffu, t, o);
        if (tid == 0) red[9] = t;
    }
    __syncthreads();
    const float stdv = sqrtf(red[9] * (1.f/512.f));
    const float inv = 1.f / (stdv + 1e-6f);
    Y[(size_t)row*D + tid      ] = g[tid]     * d0 * inv + b[tid];
    Y[(size_t)row*D + tid + 256] = g[tid+256] * d1 * inv + b[tid+256];
}

// ---------------- generic strided attention ----------------
__global__ void attn_kernel(const float* __restrict__ Q,
                            const float* __restrict__ K,
                            const float* __restrict__ V,
                            float* __restrict__ O,
                            const int* __restrict__ mask,
                            int maskMode, int maskDiv,
                            int Lq, int Lk,
                            int qDiv, int kOuter, int kDiv, int kStride,
                            float scale)
{
    extern __shared__ float sm[];
    float* Ks = sm;
    float* Vs = Ks + Lk*65;
    float* qs = Vs + Lk*65;
    float* ps = qs + 4*64;

    const int i = blockIdx.x;
    const int h = blockIdx.y;
    const int tid = threadIdx.x;
    const int lane = tid & 31;
    const int w = tid >> 5;

    const size_t kBase = (size_t)(i/kDiv)*kOuter + (size_t)(i%kDiv);

    for (int idx = tid; idx < Lk*64; idx += 128) {
        int tk = idx >> 6, d = idx & 63;
        size_t grow = (kBase + (size_t)tk*kStride)*D + h*DK + d;
        Ks[tk*65+d] = K[grow];
        Vs[tk*65+d] = V[grow];
    }
    __syncthreads();

    const int qb = (i/qDiv) * Lq;
    const int nj = (Lk + 31) >> 5;

    for (int tq = w; tq < Lq; tq += 4) {
        size_t qoff = (size_t)(qb + tq)*D + h*DK;
        qs[w*64 + lane]      = Q[qoff + lane];
        qs[w*64 + lane + 32] = Q[qoff + lane + 32];
        __syncwarp();

        float sc[4];
        #pragma unroll
        for (int j=0;j<4;j++) sc[j] = -INFINITY;

        for (int j=0;j<nj;j++) {
            int k = lane + (j<<5);
            if (k < Lk) {
                float dot = 0.f;
                const float* kr = Ks + k*65;
                const float* qq = qs + w*64;
                #pragma unroll
                for (int d=0; d<64; d++) dot += qq[d]*kr[d];
                dot *= scale;
                if (maskMode == 1) {
                    if (mask[(size_t)(i/maskDiv)*Lk + k] == 0) dot = -1e9f;
                } else if (maskMode == 2) {
                    if (mask[((size_t)i*Lq + tq)*Lk + k] == 0) dot = -1e9f;
                }
                sc[j] = dot;
            }
        }
        float mx = -INFINITY;
        for (int j=0;j<nj;j++) mx = fmaxf(mx, sc[j]);
        #pragma unroll
        for (int o=16;o>0;o>>=1) mx = fmaxf(mx, __shfl_xor_sync(0xffffffffu, mx, o));

        float e[4]; float sum = 0.f;
        for (int j=0;j<nj;j++) {
            e[j] = (sc[j] == -INFINITY) ? 0.f : __expf(sc[j] - mx);
            sum += e[j];
        }
        #pragma unroll
        for (int o=16;o>0;o>>=1) sum += __shfl_xor_sync(0xffffffffu, sum, o);
        const float inv = 1.f / sum;
        for (int j=0;j<nj;j++) {
            int k = lane + (j<<5);
            if (k < Lk) ps[w*Lk + k] = e[j] * inv;
        }
        __syncwarp();

        float o0 = 0.f, o1 = 0.f;
        for (int k=0;k<Lk;k++) {
            float p = ps[w*Lk + k];
            o0 += p * Vs[k*65 + lane];
            o1 += p * Vs[k*65 + lane + 32];
        }
        size_t orow = ((size_t)i*Lq + tq)*D + h*DK;
        O[orow + lane]      = o0;
        O[orow + lane + 32] = o1;
        __syncwarp();
    }
}

static void launch_attn(const float* Q, const float* K, const float* V, float* O,
                        const int* mask, int maskMode, int maskDiv,
                        int nb, int Lq, int Lk,
                        int qDiv, int kOuter, int kDiv, int kStride)
{
    dim3 grid(nb, NH);
    size_t smem = (size_t)(2*Lk*65 + 4*64 + 4*Lk) * sizeof(float);
    attn_kernel<<<grid, 128, smem>>>(Q, K, V, O, mask, maskMode, maskDiv,
                                     Lq, Lk, qDiv, kOuter, kDiv, kStride, 0.125f);
}

// ---------------- fold attention ----------------
__global__ void fold_attn_kernel(const float* __restrict__ O,
                                 const float* __restrict__ Qo,
                                 const float* __restrict__ sb,
                                 const int* __restrict__ mask, int maskApply,
                                 float* __restrict__ ctx, int Lk)
{
    extern __shared__ float sm[];
    float* Os = sm;               // Lk*512
    float* sc = Os + Lk*512;      // 8*64
    float* pp = sc + 512;         // 8*64

    const int u = blockIdx.x;
    const int tid = threadIdx.x;
    const int h = tid >> 5;
    const int lane = tid & 31;
    const size_t base = (size_t)(u >> 6) * Lk * 64 + (u & 63);

    for (int idx = tid; idx < Lk*512; idx += 256) {
        int s = idx >> 9, d = idx & 511;
        Os[idx] = O[(base + (size_t)s*64)*D + d];
    }
    __syncthreads();

    float qreg[16];
    #pragma unroll
    for (int i=0;i<16;i++) qreg[i] = Qo[(size_t)u*(NH*D) + h*D + i*32 + lane];

    const float sbase = sb[u*NH + h];

    for (int s = 0; s < Lk; s++) {
        float dot = 0.f;
        const float* row = Os + s*512;
        #pragma unroll
        for (int i=0;i<16;i++) dot += qreg[i] * row[i*32 + lane];
        #pragma unroll
        for (int o=16;o>0;o>>=1) dot += __shfl_xor_sync(0xffffffffu, dot, o);
        float score = (sbase + dot) * 0.125f;
        if (maskApply && mask[(u>>6)*Lk + s] == 0) score = -1e9f;
        if (lane == 0) sc[h*64 + s] = score;
    }
    __syncwarp();

    float v0 = (lane      < Lk) ? sc[h*64 + lane]      : -INFINITY;
    float v1 = (lane + 32 < Lk) ? sc[h*64 + lane + 32] : -INFINITY;
    float mx = fmaxf(v0, v1);
    #pragma unroll
    for (int o=16;o>0;o>>=1) mx = fmaxf(mx, __shfl_xor_sync(0xffffffffu, mx, o));
    float e0 = (lane      < Lk) ? __expf(v0 - mx) : 0.f;
    float e1 = (lane + 32 < Lk) ? __expf(v1 - mx) : 0.f;
    float sum = e0 + e1;
    #pragma unroll
    for (int o=16;o>0;o>>=1) sum += __shfl_xor_sync(0xffffffffu, sum, o);
    const float inv = 1.f / sum;
    if (lane      < Lk) pp[h*64 + lane]      = e0 * inv;
    if (lane + 32 < Lk) pp[h*64 + lane + 32] = e1 * inv;
    __syncwarp();

    #pragma unroll
    for (int i=0;i<16;i++) {
        float acc = 0.f;
        for (int s=0;s<Lk;s++)
            acc += pp[h*64 + s] * Os[s*512 + i*32 + lane];
        ctx[(size_t)u*(NH*D) + h*D + i*32 + lane] = acc;
    }
}

// ---------------- small helpers ----------------
__global__ void transpose512(const float* __restrict__ in, float* __restrict__ out)
{
    __shared__ float t[32][33];
    int bx = blockIdx.x*32, by = blockIdx.y*32;
    for (int j = threadIdx.y; j < 32; j += 8)
        t[j][threadIdx.x] = in[(size_t)(by+j)*D + bx + threadIdx.x];
    __syncthreads();
    for (int j = threadIdx.y; j < 32; j += 8)
        out[(size_t)(bx+j)*D + by + threadIdx.x] = t[threadIdx.x][j];
}

__global__ void addrow_kernel(const float* __restrict__ a, const float* __restrict__ bvec,
                              float* __restrict__ c)
{
    int u = blockIdx.x, d = threadIdx.x;
    c[(size_t)u*D + d] = a[(size_t)u*D + d] + bvec[d];
}

__global__ void sbase_kernel(const float* __restrict__ Qp, const float* __restrict__ mmk,
                             float* __restrict__ sb)
{
    int u = blockIdx.x;
    int h = threadIdx.x >> 5, lane = threadIdx.x & 31;
    const float* q = Qp  + (size_t)u*D + h*64;
    const float* m = mmk + (size_t)u*D + h*64;
    float s = q[lane]*m[lane] + q[lane+32]*m[lane+32];
    #pragma unroll
    for (int o=16;o>0;o>>=1) s += __shfl_xor_sync(0xffffffffu, s, o);
    if (lane == 0) sb[u*NH + h] = s;
}

__global__ void add_kernel(const float* __restrict__ a, const float* __restrict__ b,
                           float* __restrict__ c, int n)
{
    int i = blockIdx.x*256 + threadIdx.x;
    if (i < n) c[i] = a[i] + b[i];
}

// ---------------- driver ----------------
extern "C" void kernel_launch(void* const* d_in, const int* in_sizes, int n_in,
                              void* d_out, int out_size)
{
    const float* x        = (const float*)d_in[0];
    const float* vft      = (const float*)d_in[1];
    const float* enc_his  = (const float*)d_in[2];
    const float* enc_cap  = (const float*)d_in[3];
    const float* enc_qry  = (const float*)d_in[4];
    const int*   trg_mask = (const int*)  d_in[5];
    const int*   his_mask = (const int*)  d_in[6];
    const int*   cap_mask = (const int*)  d_in[7];
    const int*   qry_mask = (const int*)  d_in[8];
    const int*   tmp_mask = (const int*)  d_in[9];
    const float* attn_w   = (const float*)d_in[10];
    const float* attn_b   = (const float*)d_in[11];
    const float* ff_w1    = (const float*)d_in[12];
    const float* ff_b1    = (const float*)d_in[13];
    const float* ff_w2    = (const float*)d_in[14];
    const float* ff_b2    = (const float*)d_in[15];
    const float* ln_g     = (const float*)d_in[16];
    const float* ln_b     = (const float*)d_in[17];
    float* outp = (float*)d_out;

    float *big0,*big1,*big2,*big3,*lnb,*qb,*ob,*cur,*ts,*st,*kb,*vb,*mid;
    float *mmb,*mmk,*mmv,*sb,*qo,*ctx,*w1,*w1t,*w2;
    cudaGetSymbolAddress((void**)&big0, g_big0);
    cudaGetSymbolAddress((void**)&big1, g_big1);
    cudaGetSymbolAddress((void**)&big2, g_big2);
    cudaGetSymbolAddress((void**)&big3, g_big3);
    cudaGetSymbolAddress((void**)&lnb,  g_ln);
    cudaGetSymbolAddress((void**)&qb,   g_q);
    cudaGetSymbolAddress((void**)&ob,   g_o);
    cudaGetSymbolAddress((void**)&cur,  g_cur);
    cudaGetSymbolAddress((void**)&ts,   g_ts);
    cudaGetSymbolAddress((void**)&st,   g_st);
    cudaGetSymbolAddress((void**)&kb,   g_k);
    cudaGetSymbolAddress((void**)&vb,   g_v);
    cudaGetSymbolAddress((void**)&mid,  g_mid);
    cudaGetSymbolAddress((void**)&mmb,  g_mmb);
    cudaGetSymbolAddress((void**)&mmk,  g_mmk);
    cudaGetSymbolAddress((void**)&mmv,  g_mmv);
    cudaGetSymbolAddress((void**)&sb,   g_sb);
    cudaGetSymbolAddress((void**)&qo,   g_qo);
    cudaGetSymbolAddress((void**)&ctx,  g_ctx);
    cudaGetSymbolAddress((void**)&w1,   g_w1);
    cudaGetSymbolAddress((void**)&w1t,  g_w1t);
    cudaGetSymbolAddress((void**)&w2,   g_w2);

    cudaFuncSetAttribute(attn_kernel, cudaFuncAttributeMaxDynamicSharedMemorySize, 73728);
    cudaFuncSetAttribute(fold_attn_kernel, cudaFuncAttributeMaxDynamicSharedMemorySize, 64*512*4 + 4096);
    cudaFuncSetAttribute(tf32_gemm_big, cudaFuncAttributeMaxDynamicSharedMemorySize, 128*132*4);

    #define WATT(l,j) (attn_w + ((size_t)(l)*4+(j))*D*D)
    #define BATT(l,j) (attn_b + ((size_t)(l)*4+(j))*D)

    // ===== MHA0: self-attn, causal mask =====
    ln_kernel<<<NT,256>>>(x, ln_g + 0*D, ln_b + 0*D, lnb);
    launch_gemm(lnb,D, WATT(0,0),D, BATT(0,0), nullptr,0,0, qb,D, NT, D, D);
    launch_gemm(lnb,D, WATT(0,1),D, BATT(0,1), nullptr,0,0, kb,D, NT, D, D);
    launch_gemm(lnb,D, WATT(0,2),D, BATT(0,2), nullptr,0,0, vb,D, NT, D, D);
    launch_attn(qb, kb, vb, ob, trg_mask, 2, 1, BSZ, TTRG, TTRG, 1, TTRG, 1, 1);
    launch_gemm(ob,D, WATT(0,3),D, BATT(0,3), x,D,0, cur,D, NT, D, D);

    // ===== MHA1: cross-attn encoded_his (Lk=128) =====
    ln_kernel<<<NT,256>>>(cur, ln_g + 1*D, ln_b + 1*D, lnb);
    launch_gemm(lnb,D,     WATT(1,0),D, BATT(1,0), nullptr,0,0, qb,D, NT,   D, D);
    launch_gemm(enc_his,D, WATT(1,1),D, BATT(1,1), nullptr,0,0, kb,D, 2048, D, D);
    launch_gemm(enc_his,D, WATT(1,2),D, BATT(1,2), nullptr,0,0, vb,D, 2048, D, D);
    launch_attn(qb, kb, vb, ob, his_mask, 1, 1, BSZ, TTRG, 128, 1, 128, 1, 1);
    launch_gemm(ob,D, WATT(1,3),D, BATT(1,3), cur,D,0, cur,D, NT, D, D);

    // ===== MHA2: cross-attn encoded_cap (Lk=64) =====
    ln_kernel<<<NT,256>>>(cur, ln_g + 2*D, ln_b + 2*D, lnb);
    launch_gemm(lnb,D,     WATT(2,0),D, BATT(2,0), nullptr,0,0, qb,D, NT,   D, D);
    launch_gemm(enc_cap,D, WATT(2,1),D, BATT(2,1), nullptr,0,0, kb,D, 1024, D, D);
    launch_gemm(enc_cap,D, WATT(2,2),D, BATT(2,2), nullptr,0,0, vb,D, 1024, D, D);
    launch_attn(qb, kb, vb, ob, cap_mask, 1, 1, BSZ, TTRG, 64, 1, 64, 1, 1);
    launch_gemm(ob,D, WATT(2,3),D, BATT(2,3), cur,D,0, cur,D, NT, D, D);

    // ===== MHA3: cross-attn encoded_query (Lk=32) -> mm (cur) =====
    ln_kernel<<<NT,256>>>(cur, ln_g + 3*D, ln_b + 3*D, lnb);
    launch_gemm(lnb,D,     WATT(3,0),D, BATT(3,0), nullptr,0,0, qb,D, NT,  D, D);
    launch_gemm(enc_qry,D, WATT(3,1),D, BATT(3,1), nullptr,0,0, kb,D, 512, D, D);
    launch_gemm(enc_qry,D, WATT(3,2),D, BATT(3,2), nullptr,0,0, vb,D, 512, D, D);
    launch_attn(qb, kb, vb, ob, qry_mask, 1, 1, BSZ, TTRG, 32, 1, 32, 1, 1);
    launch_gemm(ob,D, WATT(3,3),D, BATT(3,3), cur,D,0, cur,D, NT, D, D);
    // cur == mm from here on

    // ===== temporal2spatial: MHA4 over T per spatial location =====
    ln_kernel<<<NT,256>>>(cur, ln_g + 4*D, ln_b + 4*D, lnb);
    launch_gemm(lnb,D, WATT(4,0),D, BATT(4,0), nullptr,0,0, qb,D, NT, D, D);
    launch_gemm(vft,D, WATT(4,1),D, BATT(4,1), nullptr,0,0, big0,D, NV, D, D);   // K4
    launch_gemm(vft,D, WATT(4,2),D, BATT(4,2), nullptr,0,0, big1,D, NV, D, D);   // V4
    launch_attn(qb, big0, big1, big2, tmp_mask, 1, SSP,
                BSZ*SSP, TTRG, TT, SSP, TT*SSP, SSP, SSP);                       // O4

    // ===== MHA5 (folded) =====
    {
        const float* Wo = WATT(4,3); const float* bo = BATT(4,3);
        const float* Wq = WATT(5,0), *Wk = WATT(5,1), *Wv = WATT(5,2), *Wo5 = WATT(5,3);
        addrow_kernel<<<NT,512>>>(cur, bo, mmb);
        launch_gemm(mmb,D, Wk,D, BATT(5,1), nullptr,0,0, mmk,D, NT, D, D);
        launch_gemm(mmb,D, Wv,D, BATT(5,2), nullptr,0,0, mmv,D, NT, D, D);
        ln_kernel<<<NT,256>>>(cur, ln_g + 5*D, ln_b + 5*D, lnb);
        launch_gemm(lnb,D, Wq,D, BATT(5,0), nullptr,0,0, qb,D, NT, D, D);
        launch_gemm(Wo,D, Wk,D, nullptr, nullptr,0,0, w1,D, D, D, D);
        transpose512<<<dim3(16,16),dim3(32,8)>>>(w1, w1t);
        launch_gemm(Wo,D, Wv,D, nullptr, nullptr,0,0, w2,D, D, D, D);
        for (int h=0; h<NH; h++)
            launch_gemm(qb + h*64, D, w1t + (size_t)h*64*D, D, nullptr, nullptr,0,0,
                        qo + h*D, NH*D, NT, D, 64);
        sbase_kernel<<<NT,256>>>(qb, mmk, sb);
        fold_attn_kernel<<<NT,256, SSP*512*4 + 4096>>>(big2, qo, sb, nullptr, 0, ctx, SSP);
        for (int h=0; h<NH; h++)
            launch_gemm(ctx + h*D, NH*D, w2 + h*64, D, nullptr, mmv + h*64, D, 0,
                        ob + h*64, D, NT, 64, D);
        launch_gemm(ob,D, Wo5,D, BATT(5,3), cur,D,0, ts,D, NT, D, D);
    }

    // ===== FFN0 on ts =====
    ln_kernel<<<NT,256>>>(ts, ln_g + 6*D, ln_b + 6*D, lnb);
    launch_gemm(lnb,D, ff_w1 + 0*(size_t)D*DFF,DFF, ff_b1 + 0*DFF, nullptr,0,1, mid,DFF, NT, DFF, D);
    launch_gemm(mid,DFF, ff_w2 + 0*(size_t)DFF*D,D, ff_b2 + 0*D, ts,D,0, ts,D, NT, D, DFF);

    // ===== spatial2temporal: MHA6 over S per frame =====
    ln_kernel<<<NT,256>>>(cur, ln_g + 7*D, ln_b + 7*D, lnb);
    launch_gemm(lnb,D, WATT(6,0),D, BATT(6,0), nullptr,0,0, qb,D, NT, D, D);
    launch_gemm(vft,D, WATT(6,1),D, BATT(6,1), nullptr,0,0, big0,D, NV, D, D);   // K6
    launch_gemm(vft,D, WATT(6,2),D, BATT(6,2), nullptr,0,0, big1,D, NV, D, D);   // V6
    launch_attn(qb, big0, big1, big3, nullptr, 0, 1,
                BSZ*TT, TTRG, SSP, TT, SSP, 1, 1);                               // O6 (NBIG rows)

    // ===== MHA7 (folded) =====
    {
        const float* Wo = WATT(6,3); const float* bo = BATT(6,3);
        const float* Wq = WATT(7,0), *Wk = WATT(7,1), *Wv = WATT(7,2), *Wo7 = WATT(7,3);
        addrow_kernel<<<NT,512>>>(cur, bo, mmb);
        launch_gemm(mmb,D, Wk,D, BATT(7,1), nullptr,0,0, mmk,D, NT, D, D);
        launch_gemm(mmb,D, Wv,D, BATT(7,2), nullptr,0,0, mmv,D, NT, D, D);
        ln_kernel<<<NT,256>>>(cur, ln_g + 8*D, ln_b + 8*D, lnb);
        launch_gemm(lnb,D, Wq,D, BATT(7,0), nullptr,0,0, qb,D, NT, D, D);
        launch_gemm(Wo,D, Wk,D, nullptr, nullptr,0,0, w1,D, D, D, D);
        transpose512<<<dim3(16,16),dim3(32,8)>>>(w1, w1t);
        launch_gemm(Wo,D, Wv,D, nullptr, nullptr,0,0, w2,D, D, D, D);
        for (int h=0; h<NH; h++)
            launch_gemm(qb + h*64, D, w1t + (size_t)h*64*D, D, nullptr, nullptr,0,0,
                        qo + h*D, NH*D, NT, D, 64);
        sbase_kernel<<<NT,256>>>(qb, mmk, sb);
        fold_attn_kernel<<<NT,256, TT*512*4 + 4096>>>(big3, qo, sb, tmp_mask, 1, ctx, TT);
        for (int h=0; h<NH; h++)
            launch_gemm(ctx + h*D, NH*D, w2 + h*64, D, nullptr, mmv + h*64, D, 0,
                        ob + h*64, D, NT, 64, D);
        launch_gemm(ob,D, Wo7,D, BATT(7,3), cur,D,0, st,D, NT, D, D);
    }

    // ===== FFN1 on st =====
    ln_kernel<<<NT,256>>>(st, ln_g + 9*D, ln_b + 9*D, lnb);
    launch_gemm(lnb,D, ff_w1 + 1*(size_t)D*DFF,DFF, ff_b1 + 1*DFF, nullptr,0,1, mid,DFF, NT, DFF, D);
    launch_gemm(mid,DFF, ff_w2 + 1*(size_t)DFF*D,D, ff_b2 + 1*D, st,D,0, st,D, NT, D, DFF);

    // ===== out = ts + st; FFN2 =====
    add_kernel<<<(NT*D+255)/256,256>>>(ts, st, qb, NT*D);
    ln_kernel<<<NT,256>>>(qb, ln_g + 10*D, ln_b + 10*D, lnb);
    launch_gemm(lnb,D, ff_w1 + 2*(size_t)D*DFF,DFF, ff_b1 + 2*DFF, nullptr,0,1, mid,DFF, NT, DFF, D);
    launch_gemm(mid,DFF, ff_w2 + 2*(size_t)DFF*D,D, ff_b2 + 2*D, qb,D,0, outp,D, NT, D, DFF);
}